// round 1
// baseline (speedup 1.0000x reference)
#include <cuda_runtime.h>
#include <cuda_bf16.h>
#include <cstdint>

#define DIMC 128
#define HID 512
#define TILE_M 64
#define THREADS 256
#define WSTRIDE 132   // weight chunk row stride in floats (conflict-free: 528B % 128 = 16)
#define EPSV 1e-5f

// smem layout (floats):
//   xn : [64][128]  =  8192
//   Hs : [64][512]  = 32768
//   ws : [128][132] = 16896   (weight chunk staging, reused by both GEMMs)
// total = 57856 floats = 231424 bytes  (< 232448 max dyn smem)
#define XN_OFF 0
#define HS_OFF 8192
#define WS_OFF (8192 + 32768)
#define SMEM_FLOATS (8192 + 32768 + 16896)

// packed f32x2 FMA: acc.lo += a.lo*b.lo ; acc.hi += a.hi*b.hi
__device__ __forceinline__ void ffma2(unsigned long long &acc,
                                      unsigned long long a,
                                      unsigned long long b) {
    asm("fma.rn.f32x2 %0, %1, %2, %0;" : "+l"(acc) : "l"(a), "l"(b));
}

__device__ __forceinline__ float unpack_sum(unsigned long long v) {
    float lo = __uint_as_float((unsigned)(v & 0xffffffffull));
    float hi = __uint_as_float((unsigned)(v >> 32));
    return lo + hi;
}

__global__ __launch_bounds__(THREADS, 1)
void fused_ln_mlp_kernel(const float* __restrict__ x,
                         const float* __restrict__ w1,
                         const float* __restrict__ w2,
                         const float* __restrict__ b1,
                         const float* __restrict__ b2,
                         const float* __restrict__ wn,
                         const float* __restrict__ bn,
                         float* __restrict__ out)
{
    extern __shared__ __align__(16) float smem[];
    float* xn = smem + XN_OFF;
    float* Hs = smem + HS_OFF;
    float* ws = smem + WS_OFF;

    const int tid  = threadIdx.x;
    const int lane = tid & 31;
    const int warp = tid >> 5;
    const long long m0 = (long long)blockIdx.x * TILE_M;

    // ---------------- Stage A: LayerNorm (8 tokens per warp) ----------------
    {
        const float4 wn4 = *(const float4*)(wn + lane * 4);
        const float4 bn4 = *(const float4*)(bn + lane * 4);
        #pragma unroll
        for (int t = 0; t < 8; ++t) {
            const int tok = warp * 8 + t;
            float4 v = *(const float4*)(x + (m0 + tok) * DIMC + lane * 4);
            float s = v.x + v.y + v.z + v.w;
            float q = v.x*v.x + v.y*v.y + v.z*v.z + v.w*v.w;
            #pragma unroll
            for (int o = 16; o > 0; o >>= 1) {
                s += __shfl_xor_sync(0xffffffffu, s, o);
                q += __shfl_xor_sync(0xffffffffu, q, o);
            }
            const float mu  = s * (1.0f / DIMC);
            const float var = q * (1.0f / DIMC) - mu * mu;
            const float r   = rsqrtf(var + EPSV);
            float4 o4;
            o4.x = (v.x - mu) * r * wn4.x + bn4.x;
            o4.y = (v.y - mu) * r * wn4.y + bn4.y;
            o4.z = (v.z - mu) * r * wn4.z + bn4.z;
            o4.w = (v.w - mu) * r * wn4.w + bn4.w;
            *(float4*)(xn + tok * DIMC + lane * 4) = o4;
        }
    }

    // thread mapping for both GEMMs:
    //   hb/ob = tid % 32  -> base column, thread owns columns {hb + 32*j}, j=0..3
    //   tb    = tid / 32  -> token block, thread owns tokens {tb*8 + t},   t=0..7
    // warp => fixed tb, lanes span hb  => xn/Hs reads are broadcast,
    // weight reads stride 1 row (528B apart) => conflict-free float4.
    const int hb = tid & 31;
    const int tb = tid >> 5;

    // ---------------- Stage B: H = relu(xn @ w1^T + b1) ----------------
    for (int c = 0; c < 4; ++c) {               // 4 chunks of 128 hidden units
        __syncthreads();
        // stage w1 rows [c*128, c*128+128) x 128 cols into smem
        {
            const float4* w1g = (const float4*)(w1 + (size_t)c * 128 * DIMC);
            for (int idx = tid; idx < 128 * 32; idx += THREADS) {
                const int row = idx >> 5, col = idx & 31;
                *(float4*)(ws + row * WSTRIDE + col * 4) = w1g[row * 32 + col];
            }
        }
        __syncthreads();

        unsigned long long acc[8][4];
        #pragma unroll
        for (int j = 0; j < 4; ++j) {
            const unsigned long long init =
                (unsigned long long)__float_as_uint(__ldg(b1 + c * 128 + hb + 32 * j));
            #pragma unroll
            for (int t = 0; t < 8; ++t) acc[t][j] = init;
        }

        #pragma unroll 2
        for (int kk = 0; kk < 32; ++kk) {       // 4 k's per iter
            ulonglong2 xv[8];
            #pragma unroll
            for (int t = 0; t < 8; ++t)
                xv[t] = *(const ulonglong2*)(xn + (tb * 8 + t) * DIMC + kk * 4);
            #pragma unroll
            for (int j = 0; j < 4; ++j) {
                const ulonglong2 wv =
                    *(const ulonglong2*)(ws + (hb + 32 * j) * WSTRIDE + kk * 4);
                #pragma unroll
                for (int t = 0; t < 8; ++t) {
                    ffma2(acc[t][j], xv[t].x, wv.x);
                    ffma2(acc[t][j], xv[t].y, wv.y);
                }
            }
        }

        #pragma unroll
        for (int j = 0; j < 4; ++j)
            #pragma unroll
            for (int t = 0; t < 8; ++t)
                Hs[(tb * 8 + t) * HID + c * 128 + hb + 32 * j] =
                    fmaxf(unpack_sum(acc[t][j]), 0.0f);
    }

    // ---------------- Stage C: out = H @ w2^T + b2 ----------------
    unsigned long long acc2[8][4];
    #pragma unroll
    for (int j = 0; j < 4; ++j) {
        const unsigned long long init =
            (unsigned long long)__float_as_uint(__ldg(b2 + hb + 32 * j));
        #pragma unroll
        for (int t = 0; t < 8; ++t) acc2[t][j] = init;
    }

    for (int c = 0; c < 4; ++c) {               // 4 chunks of 128 over K=512
        __syncthreads();                        // also orders Hs writes before reads (c==0)
        // stage w2[:, c*128 .. c*128+128) into smem
        for (int idx = tid; idx < 128 * 32; idx += THREADS) {
            const int row = idx >> 5, col = idx & 31;
            *(float4*)(ws + row * WSTRIDE + col * 4) =
                *(const float4*)(w2 + (size_t)row * HID + c * 128 + col * 4);
        }
        __syncthreads();

        #pragma unroll 2
        for (int kk = 0; kk < 32; ++kk) {
            ulonglong2 hv[8];
            #pragma unroll
            for (int t = 0; t < 8; ++t)
                hv[t] = *(const ulonglong2*)(Hs + (tb * 8 + t) * HID + c * 128 + kk * 4);
            #pragma unroll
            for (int j = 0; j < 4; ++j) {
                const ulonglong2 wv =
                    *(const ulonglong2*)(ws + (hb + 32 * j) * WSTRIDE + kk * 4);
                #pragma unroll
                for (int t = 0; t < 8; ++t) {
                    ffma2(acc2[t][j], hv[t].x, wv.x);
                    ffma2(acc2[t][j], hv[t].y, wv.y);
                }
            }
        }
    }

    #pragma unroll
    for (int j = 0; j < 4; ++j)
        #pragma unroll
        for (int t = 0; t < 8; ++t)
            out[(m0 + tb * 8 + t) * DIMC + hb + 32 * j] = unpack_sum(acc2[t][j]);
}

extern "C" void kernel_launch(void* const* d_in, const int* in_sizes, int n_in,
                              void* d_out, int out_size) {
    const float* x  = (const float*)d_in[0];
    const float* w1 = (const float*)d_in[1];
    const float* w2 = (const float*)d_in[2];
    const float* b1 = (const float*)d_in[3];
    const float* b2 = (const float*)d_in[4];
    const float* wn = (const float*)d_in[5];
    const float* bn = (const float*)d_in[6];
    float* out = (float*)d_out;

    const int T = in_sizes[0] / DIMC;          // 262144
    const int grid = T / TILE_M;               // 4096 CTAs

    const size_t smem = SMEM_FLOATS * sizeof(float);  // 231424 B
    cudaFuncSetAttribute(fused_ln_mlp_kernel,
                         cudaFuncAttributeMaxDynamicSharedMemorySize, (int)smem);
    fused_ln_mlp_kernel<<<grid, THREADS, smem>>>(x, w1, w2, b1, b2, wn, bn, out);
}

// round 3
// speedup vs baseline: 3.1583x; 3.1583x over previous
#include <cuda_runtime.h>
#include <cuda_bf16.h>
#include <cstdint>

#define DIMC 128
#define HID  512
#define TILE_M 128
#define THREADS 256
#define EPSV 1e-5f

#define ROWE 136                       // bf16 elems per padded row (272 B)
#define ROWB 272
#define TILE_BYTES (128 * ROWB)        // 34816

// ---- smem layout (bytes); WH/WL contiguous so weight stage is one 69632B copy
#define SM_XNH 0
#define SM_XNL (SM_XNH + TILE_BYTES)
#define SM_HCH (SM_XNL + TILE_BYTES)
#define SM_HCL (SM_HCH + TILE_BYTES)
#define SM_WH  (SM_HCL + TILE_BYTES)
#define SM_WL  (SM_WH  + TILE_BYTES)
#define SM_TOTAL (SM_WL + TILE_BYTES)  // 208896 B

// ---- pre-split, pre-padded weight images: [chunk][hi/lo][128*ROWE] bf16
__device__ __align__(16) __nv_bfloat16 g_w1[4][2][128 * ROWE];
__device__ __align__(16) __nv_bfloat16 g_w2[4][2][128 * ROWE];

// ---------------- PTX helpers (baseline ISA only, no 'a' features) ----------
__device__ __forceinline__ uint32_t smem_u32(const void* p) {
    uint32_t a;
    asm("{ .reg .u64 t; cvta.to.shared.u64 t, %1; cvt.u32.u64 %0, t; }" : "=r"(a) : "l"(p));
    return a;
}

__device__ __forceinline__ void ldsm4(uint32_t r[4], uint32_t addr) {
    asm volatile("ldmatrix.sync.aligned.m8n8.x4.shared.b16 {%0,%1,%2,%3}, [%4];"
                 : "=r"(r[0]), "=r"(r[1]), "=r"(r[2]), "=r"(r[3]) : "r"(addr));
}

__device__ __forceinline__ void mma16816(float c[4], const uint32_t a[4],
                                         uint32_t b0, uint32_t b1) {
    asm volatile(
        "mma.sync.aligned.m16n8k16.row.col.f32.bf16.bf16.f32 "
        "{%0,%1,%2,%3}, {%4,%5,%6,%7}, {%8,%9}, {%0,%1,%2,%3};"
        : "+f"(c[0]), "+f"(c[1]), "+f"(c[2]), "+f"(c[3])
        : "r"(a[0]), "r"(a[1]), "r"(a[2]), "r"(a[3]), "r"(b0), "r"(b1));
}

__device__ __forceinline__ void cpasync16(uint32_t dst, const void* src) {
    asm volatile("cp.async.cg.shared.global [%0], [%1], 16;" :: "r"(dst), "l"(src));
}
#define CP_COMMIT() asm volatile("cp.async.commit_group;" ::: "memory")
#define CP_WAIT0()  asm volatile("cp.async.wait_group 0;" ::: "memory")

__device__ __forceinline__ uint32_t pack2(__nv_bfloat16 a, __nv_bfloat16 b) {
    __nv_bfloat162 t; t.x = a; t.y = b;
    return *(uint32_t*)&t;
}

// ---------------- prep: split weights -> bf16 hi/lo padded images ----------
__global__ void prep_weights(const float* __restrict__ w1, const float* __restrict__ w2) {
    const int idx = blockIdx.x * blockDim.x + threadIdx.x;   // 0..65535
    {   // w1: [512 h][128 d]; B tile stored [n=h_local][k=d]
        const float v = w1[idx];
        const __nv_bfloat16 hi = __float2bfloat16(v);
        const __nv_bfloat16 lo = __float2bfloat16(v - __bfloat162float(hi));
        const int h = idx >> 7, d = idx & 127;
        g_w1[h >> 7][0][(h & 127) * ROWE + d] = hi;
        g_w1[h >> 7][1][(h & 127) * ROWE + d] = lo;
    }
    {   // w2: [128 d][512 h]; B tile stored [n=d][k=h_local]
        const float v = w2[idx];
        const __nv_bfloat16 hi = __float2bfloat16(v);
        const __nv_bfloat16 lo = __float2bfloat16(v - __bfloat162float(hi));
        const int d = idx >> 9, h = idx & 511;
        g_w2[h >> 7][0][d * ROWE + (h & 127)] = hi;
        g_w2[h >> 7][1][d * ROWE + (h & 127)] = lo;
    }
}

// ---------------- 128x128x128 chunk GEMM, 3-term bf16 split ----------------
// aH/aL/bH/bL are per-thread lane-resolved base addresses.
__device__ __forceinline__ void gemm_chunk(uint32_t aH, uint32_t aL,
                                           uint32_t bH, uint32_t bL,
                                           float acc[2][8][4]) {
    #pragma unroll
    for (int ks = 0; ks < 8; ++ks) {
        uint32_t a0H[4], a1H[4], a0L[4], a1L[4];
        ldsm4(a0H, aH + ks * 32);
        ldsm4(a1H, aH + 16 * ROWB + ks * 32);
        ldsm4(a0L, aL + ks * 32);
        ldsm4(a1L, aL + 16 * ROWB + ks * 32);
        #pragma unroll
        for (int ng = 0; ng < 4; ++ng) {
            uint32_t rbH[4], rbL[4];
            ldsm4(rbH, bH + ng * (16 * ROWB) + ks * 32);
            ldsm4(rbL, bL + ng * (16 * ROWB) + ks * 32);
            // hi*hi
            mma16816(acc[0][2*ng],   a0H, rbH[0], rbH[1]);
            mma16816(acc[1][2*ng],   a1H, rbH[0], rbH[1]);
            mma16816(acc[0][2*ng+1], a0H, rbH[2], rbH[3]);
            mma16816(acc[1][2*ng+1], a1H, rbH[2], rbH[3]);
            // lo*hi
            mma16816(acc[0][2*ng],   a0L, rbH[0], rbH[1]);
            mma16816(acc[1][2*ng],   a1L, rbH[0], rbH[1]);
            mma16816(acc[0][2*ng+1], a0L, rbH[2], rbH[3]);
            mma16816(acc[1][2*ng+1], a1L, rbH[2], rbH[3]);
            // hi*lo
            mma16816(acc[0][2*ng],   a0H, rbL[0], rbL[1]);
            mma16816(acc[1][2*ng],   a1H, rbL[0], rbL[1]);
            mma16816(acc[0][2*ng+1], a0H, rbL[2], rbL[3]);
            mma16816(acc[1][2*ng+1], a1H, rbL[2], rbL[3]);
        }
    }
}

// ---------------- main fused kernel ----------------
__global__ void __launch_bounds__(THREADS, 1)
fused_ln_mlp_hmma(const float* __restrict__ x,
                  const float* __restrict__ b1,
                  const float* __restrict__ b2,
                  const float* __restrict__ wn,
                  const float* __restrict__ bn,
                  float* __restrict__ out)
{
    extern __shared__ __align__(16) unsigned char smem[];
    const uint32_t sb = smem_u32(smem);

    const int tid  = threadIdx.x;
    const int lane = tid & 31;
    const int warp = tid >> 5;
    const int mw   = warp & 3;       // M block: 32 tokens
    const int nw   = warp >> 2;      // N block: 64 cols
    const long long m0 = (long long)blockIdx.x * TILE_M;

    // -------- Stage A: LayerNorm -> xn hi/lo bf16 padded tiles --------
    {
        const float4 wn4 = *(const float4*)(wn + lane * 4);
        const float4 bn4 = *(const float4*)(bn + lane * 4);
        #pragma unroll
        for (int t = 0; t < 16; ++t) {
            const int tok = warp * 16 + t;
            float4 v = *(const float4*)(x + (m0 + tok) * DIMC + lane * 4);
            float s = v.x + v.y + v.z + v.w;
            float q = v.x*v.x + v.y*v.y + v.z*v.z + v.w*v.w;
            #pragma unroll
            for (int o = 16; o > 0; o >>= 1) {
                s += __shfl_xor_sync(0xffffffffu, s, o);
                q += __shfl_xor_sync(0xffffffffu, q, o);
            }
            const float mu  = s * (1.0f / DIMC);
            const float var = q * (1.0f / DIMC) - mu * mu;
            const float r   = rsqrtf(var + EPSV);
            float nv[4];
            nv[0] = (v.x - mu) * r * wn4.x + bn4.x;
            nv[1] = (v.y - mu) * r * wn4.y + bn4.y;
            nv[2] = (v.z - mu) * r * wn4.z + bn4.z;
            nv[3] = (v.w - mu) * r * wn4.w + bn4.w;
            __nv_bfloat16 hi[4], lo[4];
            #pragma unroll
            for (int j = 0; j < 4; ++j) {
                hi[j] = __float2bfloat16(nv[j]);
                lo[j] = __float2bfloat16(nv[j] - __bfloat162float(hi[j]));
            }
            const uint32_t off = (uint32_t)tok * ROWB + lane * 8;
            *(uint2*)(smem + SM_XNH + off) = make_uint2(pack2(hi[0], hi[1]), pack2(hi[2], hi[3]));
            *(uint2*)(smem + SM_XNL + off) = make_uint2(pack2(lo[0], lo[1]), pack2(lo[2], lo[3]));
        }
    }

    // per-thread ldmatrix base addresses
    const uint32_t a_off = (uint32_t)(mw * 32 + (lane & 15)) * ROWB + ((lane >> 4) << 4);
    const uint32_t b_off = (uint32_t)(nw * 64 + (lane & 7) + ((lane >> 4) << 3)) * ROWB
                         + (((lane >> 3) & 1) << 4);

    float acc2[2][8][4];
    #pragma unroll
    for (int i = 0; i < 2; ++i)
        #pragma unroll
        for (int j = 0; j < 8; ++j)
            #pragma unroll
            for (int k = 0; k < 4; ++k) acc2[i][j][k] = 0.0f;

    __syncthreads();   // xn tiles visible

    for (int c = 0; c < 4; ++c) {
        // ---- stage w1 chunk (hi+lo, 69632 B contiguous) into WH/WL ----
        {
            const char* src = (const char*)&g_w1[c][0][0];
            #pragma unroll
            for (int i = 0; i < 17; ++i) {
                const uint32_t off = (uint32_t)(tid + i * THREADS) * 16;
                cpasync16(sb + SM_WH + off, src + off);
            }
            CP_COMMIT(); CP_WAIT0();
        }
        __syncthreads();

        // ---- G1: acc1 = xn (3-term) x w1c ----
        float acc1[2][8][4];
        #pragma unroll
        for (int i = 0; i < 2; ++i)
            #pragma unroll
            for (int j = 0; j < 8; ++j)
                #pragma unroll
                for (int k = 0; k < 4; ++k) acc1[i][j][k] = 0.0f;

        gemm_chunk(sb + SM_XNH + a_off, sb + SM_XNL + a_off,
                   sb + SM_WH  + b_off, sb + SM_WL  + b_off, acc1);
        __syncthreads();   // everyone done reading WH/WL

        // ---- epilogue G1: +b1, relu, split -> Hc tiles ----
        {
            const float* b1c = b1 + c * 128;
            #pragma unroll
            for (int mt = 0; mt < 2; ++mt) {
                const int row0 = mw * 32 + mt * 16 + (lane >> 2);
                #pragma unroll
                for (int nt = 0; nt < 8; ++nt) {
                    const int col = nw * 64 + nt * 8 + (lane & 3) * 2;
                    const float bb0 = __ldg(b1c + col), bb1 = __ldg(b1c + col + 1);
                    const float v0 = fmaxf(acc1[mt][nt][0] + bb0, 0.0f);
                    const float v1 = fmaxf(acc1[mt][nt][1] + bb1, 0.0f);
                    const float v2 = fmaxf(acc1[mt][nt][2] + bb0, 0.0f);
                    const float v3 = fmaxf(acc1[mt][nt][3] + bb1, 0.0f);
                    const __nv_bfloat16 h0 = __float2bfloat16(v0), h1 = __float2bfloat16(v1);
                    const __nv_bfloat16 h2 = __float2bfloat16(v2), h3 = __float2bfloat16(v3);
                    const __nv_bfloat16 l0 = __float2bfloat16(v0 - __bfloat162float(h0));
                    const __nv_bfloat16 l1 = __float2bfloat16(v1 - __bfloat162float(h1));
                    const __nv_bfloat16 l2 = __float2bfloat16(v2 - __bfloat162float(h2));
                    const __nv_bfloat16 l3 = __float2bfloat16(v3 - __bfloat162float(h3));
                    const uint32_t o0 = (uint32_t)row0 * ROWB + col * 2;
                    const uint32_t o1 = o0 + 8 * ROWB;
                    *(uint32_t*)(smem + SM_HCH + o0) = pack2(h0, h1);
                    *(uint32_t*)(smem + SM_HCH + o1) = pack2(h2, h3);
                    *(uint32_t*)(smem + SM_HCL + o0) = pack2(l0, l1);
                    *(uint32_t*)(smem + SM_HCL + o1) = pack2(l2, l3);
                }
            }
        }

        // ---- stage w2 chunk into WH/WL ----
        {
            const char* src = (const char*)&g_w2[c][0][0];
            #pragma unroll
            for (int i = 0; i < 17; ++i) {
                const uint32_t off = (uint32_t)(tid + i * THREADS) * 16;
                cpasync16(sb + SM_WH + off, src + off);
            }
            CP_COMMIT(); CP_WAIT0();
        }
        __syncthreads();   // Hc written + w2 staged

        // ---- G2: acc2 += Hc (3-term) x w2c ----
        gemm_chunk(sb + SM_HCH + a_off, sb + SM_HCL + a_off,
                   sb + SM_WH  + b_off, sb + SM_WL  + b_off, acc2);
        __syncthreads();   // done with WH/WL + Hc before next chunk
    }

    // -------- final epilogue: acc2 + b2 -> out --------
    #pragma unroll
    for (int mt = 0; mt < 2; ++mt) {
        const long long row0 = m0 + mw * 32 + mt * 16 + (lane >> 2);
        #pragma unroll
        for (int nt = 0; nt < 8; ++nt) {
            const int col = nw * 64 + nt * 8 + (lane & 3) * 2;
            const float bb0 = __ldg(b2 + col), bb1 = __ldg(b2 + col + 1);
            float2 u, w;
            u.x = acc2[mt][nt][0] + bb0;  u.y = acc2[mt][nt][1] + bb1;
            w.x = acc2[mt][nt][2] + bb0;  w.y = acc2[mt][nt][3] + bb1;
            *(float2*)(out + row0 * DIMC + col)       = u;
            *(float2*)(out + (row0 + 8) * DIMC + col) = w;
        }
    }
}

extern "C" void kernel_launch(void* const* d_in, const int* in_sizes, int n_in,
                              void* d_out, int out_size) {
    const float* x  = (const float*)d_in[0];
    const float* w1 = (const float*)d_in[1];
    const float* w2 = (const float*)d_in[2];
    const float* b1 = (const float*)d_in[3];
    const float* b2 = (const float*)d_in[4];
    const float* wn = (const float*)d_in[5];
    const float* bn = (const float*)d_in[6];
    float* out = (float*)d_out;

    prep_weights<<<256, 256>>>(w1, w2);

    const int T = in_sizes[0] / DIMC;        // 262144 tokens
    const int grid = T / TILE_M;             // 2048 CTAs

    cudaFuncSetAttribute(fused_ln_mlp_hmma,
                         cudaFuncAttributeMaxDynamicSharedMemorySize, SM_TOTAL);
    fused_ln_mlp_hmma<<<grid, THREADS, SM_TOTAL>>>(x, b1, b2, wn, bn, out);
}

// round 4
// speedup vs baseline: 4.5928x; 1.4542x over previous
#include <cuda_runtime.h>
#include <cuda_fp16.h>
#include <cstdint>

#define DIMC 128
#define HID  512
#define TILE_M 128
#define THREADS 256
#define EPSV 1e-5f

#define ROWE 136                       // fp16 elems per padded row (272 B)
#define ROWB 272
#define TILE_BYTES (128 * ROWB)        // 34816

// ---- smem layout (bytes)
#define SM_XNH 0
#define SM_XNL (SM_XNH + TILE_BYTES)
#define SM_HCH (SM_XNL + TILE_BYTES)
#define SM_HCL (SM_HCH + TILE_BYTES)
#define SM_W0  (SM_HCL + TILE_BYTES)   // w1 chunk buffer
#define SM_W1  (SM_W0  + TILE_BYTES)   // w2 chunk buffer
#define SM_TOTAL (SM_W1 + TILE_BYTES)  // 208896 B

// ---- pre-converted fp16 weight images (weights NOT split: 2-term scheme)
__device__ __align__(16) __half g_w1[4][128 * ROWE];
__device__ __align__(16) __half g_w2[4][128 * ROWE];

// ---------------- PTX helpers (baseline ISA only) ----------
__device__ __forceinline__ uint32_t smem_u32(const void* p) {
    uint32_t a;
    asm("{ .reg .u64 t; cvta.to.shared.u64 t, %1; cvt.u32.u64 %0, t; }" : "=r"(a) : "l"(p));
    return a;
}

__device__ __forceinline__ void ldsm4(uint32_t r[4], uint32_t addr) {
    asm volatile("ldmatrix.sync.aligned.m8n8.x4.shared.b16 {%0,%1,%2,%3}, [%4];"
                 : "=r"(r[0]), "=r"(r[1]), "=r"(r[2]), "=r"(r[3]) : "r"(addr));
}

__device__ __forceinline__ void mma16816(float c[4], const uint32_t a[4],
                                         uint32_t b0, uint32_t b1) {
    asm volatile(
        "mma.sync.aligned.m16n8k16.row.col.f32.f16.f16.f32 "
        "{%0,%1,%2,%3}, {%4,%5,%6,%7}, {%8,%9}, {%0,%1,%2,%3};"
        : "+f"(c[0]), "+f"(c[1]), "+f"(c[2]), "+f"(c[3])
        : "r"(a[0]), "r"(a[1]), "r"(a[2]), "r"(a[3]), "r"(b0), "r"(b1));
}

__device__ __forceinline__ void cpasync16(uint32_t dst, const void* src) {
    asm volatile("cp.async.cg.shared.global [%0], [%1], 16;" :: "r"(dst), "l"(src));
}
#define CP_COMMIT() asm volatile("cp.async.commit_group;" ::: "memory")
#define CP_WAIT0()  asm volatile("cp.async.wait_group 0;" ::: "memory")
#define CP_WAIT1()  asm volatile("cp.async.wait_group 1;" ::: "memory")

__device__ __forceinline__ uint32_t pack2(__half a, __half b) {
    __half2 t; t.x = a; t.y = b;
    return *(uint32_t*)&t;
}

// stage one 34816 B weight tile (gmem -> smem) as one cp.async group
__device__ __forceinline__ void stage_tile(uint32_t dst, const void* src, int tid) {
    #pragma unroll
    for (int i = 0; i < 8; ++i) {
        const uint32_t off = (uint32_t)(tid + i * THREADS) * 16;
        cpasync16(dst + off, (const char*)src + off);
    }
    if (tid < 128) {
        const uint32_t off = (uint32_t)(tid + 2048) * 16;
        cpasync16(dst + off, (const char*)src + off);
    }
    CP_COMMIT();
}

// ---------------- prep: weights -> fp16 padded images ----------
__global__ void prep_weights(const float* __restrict__ w1, const float* __restrict__ w2) {
    const int idx = blockIdx.x * blockDim.x + threadIdx.x;   // 0..65535
    {   // w1: [512 h][128 d]; B tile stored [n=h_local][k=d]
        const int h = idx >> 7, d = idx & 127;
        g_w1[h >> 7][(h & 127) * ROWE + d] = __float2half_rn(w1[idx]);
    }
    {   // w2: [128 d][512 h]; B tile stored [n=d][k=h_local]
        const int d = idx >> 9, h = idx & 511;
        g_w2[h >> 7][d * ROWE + (h & 127)] = __float2half_rn(w2[idx]);
    }
}

// ---------------- 128x128x128 chunk GEMM, 2-term fp16 split (A only) --------
__device__ __forceinline__ void gemm_chunk(uint32_t aH, uint32_t aL, uint32_t bH,
                                           float acc[2][8][4]) {
    #pragma unroll
    for (int ks = 0; ks < 8; ++ks) {
        uint32_t a0H[4], a1H[4], a0L[4], a1L[4];
        ldsm4(a0H, aH + ks * 32);
        ldsm4(a1H, aH + 16 * ROWB + ks * 32);
        ldsm4(a0L, aL + ks * 32);
        ldsm4(a1L, aL + 16 * ROWB + ks * 32);
        #pragma unroll
        for (int ng = 0; ng < 4; ++ng) {
            uint32_t rb[4];
            ldsm4(rb, bH + ng * (16 * ROWB) + ks * 32);
            // hi*b
            mma16816(acc[0][2*ng],   a0H, rb[0], rb[1]);
            mma16816(acc[1][2*ng],   a1H, rb[0], rb[1]);
            mma16816(acc[0][2*ng+1], a0H, rb[2], rb[3]);
            mma16816(acc[1][2*ng+1], a1H, rb[2], rb[3]);
            // lo*b
            mma16816(acc[0][2*ng],   a0L, rb[0], rb[1]);
            mma16816(acc[1][2*ng],   a1L, rb[0], rb[1]);
            mma16816(acc[0][2*ng+1], a0L, rb[2], rb[3]);
            mma16816(acc[1][2*ng+1], a1L, rb[2], rb[3]);
        }
    }
}

// ---------------- main fused kernel ----------------
__global__ void __launch_bounds__(THREADS, 1)
fused_ln_mlp_hmma(const float* __restrict__ x,
                  const float* __restrict__ b1,
                  const float* __restrict__ b2,
                  const float* __restrict__ wn,
                  const float* __restrict__ bn,
                  float* __restrict__ out)
{
    extern __shared__ __align__(16) unsigned char smem[];
    const uint32_t sb = smem_u32(smem);

    const int tid  = threadIdx.x;
    const int lane = tid & 31;
    const int warp = tid >> 5;
    const int mw   = warp & 3;       // M block: 32 tokens
    const int nw   = warp >> 2;      // N block: 64 cols
    const long long m0 = (long long)blockIdx.x * TILE_M;

    // prefetch w1(0) immediately; LN overlaps the copy
    stage_tile(sb + SM_W0, &g_w1[0][0], tid);   // group: tile0

    // -------- Stage A: LayerNorm -> xn hi/lo fp16 padded tiles --------
    {
        const float4 wn4 = *(const float4*)(wn + lane * 4);
        const float4 bn4 = *(const float4*)(bn + lane * 4);
        #pragma unroll
        for (int t = 0; t < 16; ++t) {
            const int tok = warp * 16 + t;
            float4 v = *(const float4*)(x + (m0 + tok) * DIMC + lane * 4);
            float s = v.x + v.y + v.z + v.w;
            float q = v.x*v.x + v.y*v.y + v.z*v.z + v.w*v.w;
            #pragma unroll
            for (int o = 16; o > 0; o >>= 1) {
                s += __shfl_xor_sync(0xffffffffu, s, o);
                q += __shfl_xor_sync(0xffffffffu, q, o);
            }
            const float mu  = s * (1.0f / DIMC);
            const float var = q * (1.0f / DIMC) - mu * mu;
            const float r   = rsqrtf(var + EPSV);
            float nv[4];
            nv[0] = (v.x - mu) * r * wn4.x + bn4.x;
            nv[1] = (v.y - mu) * r * wn4.y + bn4.y;
            nv[2] = (v.z - mu) * r * wn4.z + bn4.z;
            nv[3] = (v.w - mu) * r * wn4.w + bn4.w;
            __half hi[4], lo[4];
            #pragma unroll
            for (int j = 0; j < 4; ++j) {
                hi[j] = __float2half_rn(nv[j]);
                lo[j] = __float2half_rn(nv[j] - __half2float(hi[j]));
            }
            const uint32_t off = (uint32_t)tok * ROWB + lane * 8;
            *(uint2*)(smem + SM_XNH + off) = make_uint2(pack2(hi[0], hi[1]), pack2(hi[2], hi[3]));
            *(uint2*)(smem + SM_XNL + off) = make_uint2(pack2(lo[0], lo[1]), pack2(lo[2], lo[3]));
        }
    }

    // prefetch w2(0), then wait for w1(0) (1 group may stay pending)
    stage_tile(sb + SM_W1, &g_w2[0][0], tid);   // group: tile1
    CP_WAIT1();
    __syncthreads();   // xn tiles + w1(0) visible

    // per-thread ldmatrix base addresses
    const uint32_t a_off = (uint32_t)(mw * 32 + (lane & 15)) * ROWB + ((lane >> 4) << 4);
    const uint32_t b_off = (uint32_t)(nw * 64 + (lane & 7) + ((lane >> 4) << 3)) * ROWB
                         + (((lane >> 3) & 1) << 4);

    float acc2[2][8][4];
    #pragma unroll
    for (int i = 0; i < 2; ++i)
        #pragma unroll
        for (int j = 0; j < 8; ++j)
            #pragma unroll
            for (int k = 0; k < 4; ++k) acc2[i][j][k] = 0.0f;

    for (int c = 0; c < 4; ++c) {
        // ---- G1: acc1 = xn (2-term) x w1c ----
        float acc1[2][8][4];
        #pragma unroll
        for (int i = 0; i < 2; ++i)
            #pragma unroll
            for (int j = 0; j < 8; ++j)
                #pragma unroll
                for (int k = 0; k < 4; ++k) acc1[i][j][k] = 0.0f;

        gemm_chunk(sb + SM_XNH + a_off, sb + SM_XNL + a_off, sb + SM_W0 + b_off, acc1);

        // ---- epilogue G1: +b1, relu, split -> Hc tiles ----
        {
            const float* b1c = b1 + c * 128;
            #pragma unroll
            for (int mt = 0; mt < 2; ++mt) {
                const int row0 = mw * 32 + mt * 16 + (lane >> 2);
                #pragma unroll
                for (int nt = 0; nt < 8; ++nt) {
                    const int col = nw * 64 + nt * 8 + (lane & 3) * 2;
                    const float bb0 = __ldg(b1c + col), bb1 = __ldg(b1c + col + 1);
                    const float v0 = fmaxf(acc1[mt][nt][0] + bb0, 0.0f);
                    const float v1 = fmaxf(acc1[mt][nt][1] + bb1, 0.0f);
                    const float v2 = fmaxf(acc1[mt][nt][2] + bb0, 0.0f);
                    const float v3 = fmaxf(acc1[mt][nt][3] + bb1, 0.0f);
                    const __half h0 = __float2half_rn(v0), h1 = __float2half_rn(v1);
                    const __half h2 = __float2half_rn(v2), h3 = __float2half_rn(v3);
                    const __half l0 = __float2half_rn(v0 - __half2float(h0));
                    const __half l1 = __float2half_rn(v1 - __half2float(h1));
                    const __half l2 = __float2half_rn(v2 - __half2float(h2));
                    const __half l3 = __float2half_rn(v3 - __half2float(h3));
                    const uint32_t o0 = (uint32_t)row0 * ROWB + col * 2;
                    const uint32_t o1 = o0 + 8 * ROWB;
                    *(uint32_t*)(smem + SM_HCH + o0) = pack2(h0, h1);
                    *(uint32_t*)(smem + SM_HCH + o1) = pack2(h2, h3);
                    *(uint32_t*)(smem + SM_HCL + o0) = pack2(l0, l1);
                    *(uint32_t*)(smem + SM_HCL + o1) = pack2(l2, l3);
                }
            }
        }
        __syncthreads();   // Hc visible; all warps done reading W0

        // prefetch w1(c+1) into W0 (its reader, G1(c+1), is after the next waits)
        if (c < 3) stage_tile(sb + SM_W0, &g_w1[c + 1][0], tid);

        // ensure w2(c) landed (the only older pending group)
        if (c < 3) CP_WAIT1(); else CP_WAIT0();
        __syncthreads();

        // ---- G2: acc2 += Hc (2-term) x w2c ----
        gemm_chunk(sb + SM_HCH + a_off, sb + SM_HCL + a_off, sb + SM_W1 + b_off, acc2);
        __syncthreads();   // done reading W1 + Hc

        // prefetch w2(c+1) into W1
        if (c < 3) {
            stage_tile(sb + SM_W1, &g_w2[c + 1][0], tid);
            CP_WAIT1();      // w1(c+1) done (pending: w2(c+1))
            __syncthreads();
        }
    }

    // -------- final epilogue: acc2 + b2 -> out --------
    #pragma unroll
    for (int mt = 0; mt < 2; ++mt) {
        const long long row0 = m0 + mw * 32 + mt * 16 + (lane >> 2);
        #pragma unroll
        for (int nt = 0; nt < 8; ++nt) {
            const int col = nw * 64 + nt * 8 + (lane & 3) * 2;
            const float bb0 = __ldg(b2 + col), bb1 = __ldg(b2 + col + 1);
            float2 u, w;
            u.x = acc2[mt][nt][0] + bb0;  u.y = acc2[mt][nt][1] + bb1;
            w.x = acc2[mt][nt][2] + bb0;  w.y = acc2[mt][nt][3] + bb1;
            *(float2*)(out + row0 * DIMC + col)       = u;
            *(float2*)(out + (row0 + 8) * DIMC + col) = w;
        }
    }
}

extern "C" void kernel_launch(void* const* d_in, const int* in_sizes, int n_in,
                              void* d_out, int out_size) {
    const float* x  = (const float*)d_in[0];
    const float* w1 = (const float*)d_in[1];
    const float* w2 = (const float*)d_in[2];
    const float* b1 = (const float*)d_in[3];
    const float* b2 = (const float*)d_in[4];
    const float* wn = (const float*)d_in[5];
    const float* bn = (const float*)d_in[6];
    float* out = (float*)d_out;

    prep_weights<<<256, 256>>>(w1, w2);

    const int T = in_sizes[0] / DIMC;        // 262144 tokens
    const int grid = T / TILE_M;             // 2048 CTAs

    cudaFuncSetAttribute(fused_ln_mlp_hmma,
                         cudaFuncAttributeMaxDynamicSharedMemorySize, SM_TOTAL);
    fused_ln_mlp_hmma<<<grid, THREADS, SM_TOTAL>>>(x, b1, b2, wn, bn, out);
}

// round 5
// speedup vs baseline: 4.9498x; 1.0777x over previous
#include <cuda_runtime.h>
#include <cuda_fp16.h>
#include <cstdint>

#define DIMC 128
#define HID  512
#define TILE_M 64
#define THREADS 256
#define EPSV 1e-5f

#define ROWE 136                       // fp16 elems per padded row (272 B)
#define ROWB 272
#define ATILE_BYTES (64 * ROWB)        // 17408 (activation tiles, 64 rows)
#define WTILE_BYTES (128 * ROWB)       // 34816 (weight tiles, 128 rows)

// ---- smem layout (bytes): 104448 total -> 2 CTAs/SM
#define SM_XNH 0
#define SM_XNL (SM_XNH + ATILE_BYTES)
#define SM_HCH (SM_XNL + ATILE_BYTES)
#define SM_HCL (SM_HCH + ATILE_BYTES)
#define SM_W   (SM_HCL + ATILE_BYTES)
#define SM_TOTAL (SM_W + WTILE_BYTES)  // 104448 B

// ---- pre-converted fp16 weight images (2-term scheme: weights not split)
__device__ __align__(16) __half g_w1[4][128 * ROWE];
__device__ __align__(16) __half g_w2[4][128 * ROWE];

// ---------------- PTX helpers (baseline ISA only) ----------
__device__ __forceinline__ uint32_t smem_u32(const void* p) {
    uint32_t a;
    asm("{ .reg .u64 t; cvta.to.shared.u64 t, %1; cvt.u32.u64 %0, t; }" : "=r"(a) : "l"(p));
    return a;
}

__device__ __forceinline__ void ldsm4(uint32_t r[4], uint32_t addr) {
    asm volatile("ldmatrix.sync.aligned.m8n8.x4.shared.b16 {%0,%1,%2,%3}, [%4];"
                 : "=r"(r[0]), "=r"(r[1]), "=r"(r[2]), "=r"(r[3]) : "r"(addr));
}

__device__ __forceinline__ void mma16816(float c[4], const uint32_t a[4],
                                         uint32_t b0, uint32_t b1) {
    asm volatile(
        "mma.sync.aligned.m16n8k16.row.col.f32.f16.f16.f32 "
        "{%0,%1,%2,%3}, {%4,%5,%6,%7}, {%8,%9}, {%0,%1,%2,%3};"
        : "+f"(c[0]), "+f"(c[1]), "+f"(c[2]), "+f"(c[3])
        : "r"(a[0]), "r"(a[1]), "r"(a[2]), "r"(a[3]), "r"(b0), "r"(b1));
}

__device__ __forceinline__ void cpasync16(uint32_t dst, const void* src) {
    asm volatile("cp.async.cg.shared.global [%0], [%1], 16;" :: "r"(dst), "l"(src));
}
#define CP_COMMIT() asm volatile("cp.async.commit_group;" ::: "memory")
#define CP_WAIT0()  asm volatile("cp.async.wait_group 0;" ::: "memory")

__device__ __forceinline__ uint32_t pack2(__half a, __half b) {
    __half2 t; t.x = a; t.y = b;
    return *(uint32_t*)&t;
}

// stage one 34816 B weight tile (gmem -> smem)
__device__ __forceinline__ void stage_tile(uint32_t dst, const void* src, int tid) {
    #pragma unroll
    for (int i = 0; i < 8; ++i) {
        const uint32_t off = (uint32_t)(tid + i * THREADS) * 16;
        cpasync16(dst + off, (const char*)src + off);
    }
    if (tid < 128) {
        const uint32_t off = (uint32_t)(tid + 2048) * 16;
        cpasync16(dst + off, (const char*)src + off);
    }
    CP_COMMIT();
}

// ---------------- prep: weights -> fp16 padded images ----------
__global__ void prep_weights(const float* __restrict__ w1, const float* __restrict__ w2) {
    const int idx = blockIdx.x * blockDim.x + threadIdx.x;   // 0..65535
    {   // w1: [512 h][128 d]; B tile stored [n=h_local][k=d]
        const int h = idx >> 7, d = idx & 127;
        g_w1[h >> 7][(h & 127) * ROWE + d] = __float2half_rn(w1[idx]);
    }
    {   // w2: [128 d][512 h]; B tile stored [n=d][k=h_local]
        const int d = idx >> 9, h = idx & 511;
        g_w2[h >> 7][d * ROWE + (h & 127)] = __float2half_rn(w2[idx]);
    }
}

// ---------------- 64x128x128 chunk GEMM, 2-term fp16 split (A only) --------
// warp tile: M32 x N32. acc[2 mt][4 nt][4]
__device__ __forceinline__ void gemm_chunk(uint32_t aH, uint32_t aL, uint32_t bB,
                                           float acc[2][4][4]) {
    #pragma unroll
    for (int ks = 0; ks < 8; ++ks) {
        uint32_t a0H[4], a1H[4], a0L[4], a1L[4];
        ldsm4(a0H, aH + ks * 32);
        ldsm4(a1H, aH + 16 * ROWB + ks * 32);
        ldsm4(a0L, aL + ks * 32);
        ldsm4(a1L, aL + 16 * ROWB + ks * 32);
        #pragma unroll
        for (int ng = 0; ng < 2; ++ng) {
            uint32_t rb[4];
            ldsm4(rb, bB + ng * (16 * ROWB) + ks * 32);
            mma16816(acc[0][2*ng],   a0H, rb[0], rb[1]);
            mma16816(acc[1][2*ng],   a1H, rb[0], rb[1]);
            mma16816(acc[0][2*ng+1], a0H, rb[2], rb[3]);
            mma16816(acc[1][2*ng+1], a1H, rb[2], rb[3]);
            mma16816(acc[0][2*ng],   a0L, rb[0], rb[1]);
            mma16816(acc[1][2*ng],   a1L, rb[0], rb[1]);
            mma16816(acc[0][2*ng+1], a0L, rb[2], rb[3]);
            mma16816(acc[1][2*ng+1], a1L, rb[2], rb[3]);
        }
    }
}

// ---------------- main fused kernel ----------------
__global__ void __launch_bounds__(THREADS, 2)
fused_ln_mlp_hmma(const float* __restrict__ x,
                  const float* __restrict__ b1,
                  const float* __restrict__ b2,
                  const float* __restrict__ wn,
                  const float* __restrict__ bn,
                  float* __restrict__ out)
{
    extern __shared__ __align__(16) unsigned char smem[];
    const uint32_t sb = smem_u32(smem);

    const int tid  = threadIdx.x;
    const int lane = tid & 31;
    const int warp = tid >> 5;
    const int mw   = warp & 1;       // M block: 32 tokens
    const int nw   = warp >> 1;      // N block: 32 cols
    const long long m0 = (long long)blockIdx.x * TILE_M;

    // prefetch w1(0); LN overlaps the copy
    stage_tile(sb + SM_W, &g_w1[0][0], tid);

    // -------- Stage A: LayerNorm -> xn hi/lo fp16 padded tiles --------
    {
        const float4 wn4 = *(const float4*)(wn + lane * 4);
        const float4 bn4 = *(const float4*)(bn + lane * 4);
        #pragma unroll
        for (int t = 0; t < 8; ++t) {
            const int tok = warp * 8 + t;
            float4 v = *(const float4*)(x + (m0 + tok) * DIMC + lane * 4);
            float s = v.x + v.y + v.z + v.w;
            float q = v.x*v.x + v.y*v.y + v.z*v.z + v.w*v.w;
            #pragma unroll
            for (int o = 16; o > 0; o >>= 1) {
                s += __shfl_xor_sync(0xffffffffu, s, o);
                q += __shfl_xor_sync(0xffffffffu, q, o);
            }
            const float mu  = s * (1.0f / DIMC);
            const float var = q * (1.0f / DIMC) - mu * mu;
            const float r   = rsqrtf(var + EPSV);
            float nv[4];
            nv[0] = (v.x - mu) * r * wn4.x + bn4.x;
            nv[1] = (v.y - mu) * r * wn4.y + bn4.y;
            nv[2] = (v.z - mu) * r * wn4.z + bn4.z;
            nv[3] = (v.w - mu) * r * wn4.w + bn4.w;
            __half hi[4], lo[4];
            #pragma unroll
            for (int j = 0; j < 4; ++j) {
                hi[j] = __float2half_rn(nv[j]);
                lo[j] = __float2half_rn(nv[j] - __half2float(hi[j]));
            }
            const uint32_t off = (uint32_t)tok * ROWB + lane * 8;
            *(uint2*)(smem + SM_XNH + off) = make_uint2(pack2(hi[0], hi[1]), pack2(hi[2], hi[3]));
            *(uint2*)(smem + SM_XNL + off) = make_uint2(pack2(lo[0], lo[1]), pack2(lo[2], lo[3]));
        }
    }

    CP_WAIT0();
    __syncthreads();   // xn tiles + w1(0) visible

    // per-thread ldmatrix base addresses
    const uint32_t a_off = (uint32_t)(mw * 32 + (lane & 15)) * ROWB + ((lane >> 4) << 4);
    const uint32_t b_off = (uint32_t)(nw * 32 + (lane & 7) + ((lane >> 4) << 3)) * ROWB
                         + (((lane >> 3) & 1) << 4);

    float acc2[2][4][4];
    #pragma unroll
    for (int i = 0; i < 2; ++i)
        #pragma unroll
        for (int j = 0; j < 4; ++j)
            #pragma unroll
            for (int k = 0; k < 4; ++k) acc2[i][j][k] = 0.0f;

    for (int c = 0; c < 4; ++c) {
        // ---- G1: acc1 = xn (2-term) x w1c ----
        float acc1[2][4][4];
        #pragma unroll
        for (int i = 0; i < 2; ++i)
            #pragma unroll
            for (int j = 0; j < 4; ++j)
                #pragma unroll
                for (int k = 0; k < 4; ++k) acc1[i][j][k] = 0.0f;

        gemm_chunk(sb + SM_XNH + a_off, sb + SM_XNL + a_off, sb + SM_W + b_off, acc1);

        // ---- epilogue G1: +b1, relu, split -> Hc tiles (no W dependency) ----
        {
            const float* b1c = b1 + c * 128;
            #pragma unroll
            for (int mt = 0; mt < 2; ++mt) {
                const int row0 = mw * 32 + mt * 16 + (lane >> 2);
                #pragma unroll
                for (int nt = 0; nt < 4; ++nt) {
                    const int col = nw * 32 + nt * 8 + (lane & 3) * 2;
                    const float bb0 = __ldg(b1c + col), bb1 = __ldg(b1c + col + 1);
                    const float v0 = fmaxf(acc1[mt][nt][0] + bb0, 0.0f);
                    const float v1 = fmaxf(acc1[mt][nt][1] + bb1, 0.0f);
                    const float v2 = fmaxf(acc1[mt][nt][2] + bb0, 0.0f);
                    const float v3 = fmaxf(acc1[mt][nt][3] + bb1, 0.0f);
                    const __half h0 = __float2half_rn(v0), h1 = __float2half_rn(v1);
                    const __half h2 = __float2half_rn(v2), h3 = __float2half_rn(v3);
                    const __half l0 = __float2half_rn(v0 - __half2float(h0));
                    const __half l1 = __float2half_rn(v1 - __half2float(h1));
                    const __half l2 = __float2half_rn(v2 - __half2float(h2));
                    const __half l3 = __float2half_rn(v3 - __half2float(h3));
                    const uint32_t o0 = (uint32_t)row0 * ROWB + col * 2;
                    const uint32_t o1 = o0 + 8 * ROWB;
                    *(uint32_t*)(smem + SM_HCH + o0) = pack2(h0, h1);
                    *(uint32_t*)(smem + SM_HCH + o1) = pack2(h2, h3);
                    *(uint32_t*)(smem + SM_HCL + o0) = pack2(l0, l1);
                    *(uint32_t*)(smem + SM_HCL + o1) = pack2(l2, l3);
                }
            }
        }
        __syncthreads();   // all warps done G1 (W free) + Hc visible

        // ---- stage w2(c) over W ----
        stage_tile(sb + SM_W, &g_w2[c][0], tid);
        CP_WAIT0();
        __syncthreads();

        // ---- G2: acc2 += Hc (2-term) x w2c ----
        gemm_chunk(sb + SM_HCH + a_off, sb + SM_HCL + a_off, sb + SM_W + b_off, acc2);
        __syncthreads();   // all warps done reading W + Hc

        // ---- stage w1(c+1) ----
        if (c < 3) {
            stage_tile(sb + SM_W, &g_w1[c + 1][0], tid);
            CP_WAIT0();
            __syncthreads();
        }
    }

    // -------- final epilogue: acc2 + b2 -> out --------
    #pragma unroll
    for (int mt = 0; mt < 2; ++mt) {
        const long long row0 = m0 + mw * 32 + mt * 16 + (lane >> 2);
        #pragma unroll
        for (int nt = 0; nt < 4; ++nt) {
            const int col = nw * 32 + nt * 8 + (lane & 3) * 2;
            const float bb0 = __ldg(b2 + col), bb1 = __ldg(b2 + col + 1);
            float2 u, w;
            u.x = acc2[mt][nt][0] + bb0;  u.y = acc2[mt][nt][1] + bb1;
            w.x = acc2[mt][nt][2] + bb0;  w.y = acc2[mt][nt][3] + bb1;
            *(float2*)(out + row0 * DIMC + col)       = u;
            *(float2*)(out + (row0 + 8) * DIMC + col) = w;
        }
    }
}

extern "C" void kernel_launch(void* const* d_in, const int* in_sizes, int n_in,
                              void* d_out, int out_size) {
    const float* x  = (const float*)d_in[0];
    const float* w1 = (const float*)d_in[1];
    const float* w2 = (const float*)d_in[2];
    const float* b1 = (const float*)d_in[3];
    const float* b2 = (const float*)d_in[4];
    const float* wn = (const float*)d_in[5];
    const float* bn = (const float*)d_in[6];
    float* out = (float*)d_out;

    prep_weights<<<256, 256>>>(w1, w2);

    const int T = in_sizes[0] / DIMC;        // 262144 tokens
    const int grid = T / TILE_M;             // 4096 CTAs

    cudaFuncSetAttribute(fused_ln_mlp_hmma,
                         cudaFuncAttributeMaxDynamicSharedMemorySize, SM_TOTAL);
    fused_ln_mlp_hmma<<<grid, THREADS, SM_TOTAL>>>(x, b1, b2, wn, bn, out);
}

// round 6
// speedup vs baseline: 7.8809x; 1.5921x over previous
#include <cuda_runtime.h>
#include <cuda_fp16.h>
#include <cstdint>

#define DIMC 128
#define HID  512
#define TILE_M 64
#define THREADS 128
#define EPSV 1e-5f

#define ROWE 136                       // fp16 elems per padded row (272 B)
#define ROWB 272
#define ATILE_BYTES (64 * ROWB)        // 17408
#define WTILE_BYTES (128 * ROWB)       // 34816

// ---- smem layout (bytes): 69632 total -> 2 CTAs/SM (reg-limited)
#define SM_XNH 0
#define SM_HCH (SM_XNH + ATILE_BYTES)
#define SM_W   (SM_HCH + ATILE_BYTES)
#define SM_TOTAL (SM_W + WTILE_BYTES)  // 69632 B

// ---- pre-converted fp16 weight images
__device__ __align__(16) __half g_w1[4][128 * ROWE];
__device__ __align__(16) __half g_w2[4][128 * ROWE];

// ---------------- PTX helpers (baseline ISA only) ----------
__device__ __forceinline__ uint32_t smem_u32(const void* p) {
    uint32_t a;
    asm("{ .reg .u64 t; cvta.to.shared.u64 t, %1; cvt.u32.u64 %0, t; }" : "=r"(a) : "l"(p));
    return a;
}

__device__ __forceinline__ void ldsm4(uint32_t r[4], uint32_t addr) {
    asm volatile("ldmatrix.sync.aligned.m8n8.x4.shared.b16 {%0,%1,%2,%3}, [%4];"
                 : "=r"(r[0]), "=r"(r[1]), "=r"(r[2]), "=r"(r[3]) : "r"(addr));
}

__device__ __forceinline__ void mma16816(float c[4], const uint32_t a[4],
                                         uint32_t b0, uint32_t b1) {
    asm volatile(
        "mma.sync.aligned.m16n8k16.row.col.f32.f16.f16.f32 "
        "{%0,%1,%2,%3}, {%4,%5,%6,%7}, {%8,%9}, {%0,%1,%2,%3};"
        : "+f"(c[0]), "+f"(c[1]), "+f"(c[2]), "+f"(c[3])
        : "r"(a[0]), "r"(a[1]), "r"(a[2]), "r"(a[3]), "r"(b0), "r"(b1));
}

__device__ __forceinline__ void cpasync16(uint32_t dst, const void* src) {
    asm volatile("cp.async.cg.shared.global [%0], [%1], 16;" :: "r"(dst), "l"(src));
}
#define CP_COMMIT() asm volatile("cp.async.commit_group;" ::: "memory")
#define CP_WAIT0()  asm volatile("cp.async.wait_group 0;" ::: "memory")

__device__ __forceinline__ uint32_t pack2(__half a, __half b) {
    __half2 t; t.x = a; t.y = b;
    return *(uint32_t*)&t;
}

// stage one 34816 B weight tile (gmem -> smem): 2176 x 16B, 17 per thread
__device__ __forceinline__ void stage_tile(uint32_t dst, const void* src, int tid) {
    #pragma unroll
    for (int i = 0; i < 17; ++i) {
        const uint32_t off = (uint32_t)(tid + i * THREADS) * 16;
        cpasync16(dst + off, (const char*)src + off);
    }
    CP_COMMIT();
}

// ---------------- prep: weights -> fp16 padded images ----------
__global__ void prep_weights(const float* __restrict__ w1, const float* __restrict__ w2) {
    const int idx = blockIdx.x * blockDim.x + threadIdx.x;   // 0..65535
    {   // w1: [512 h][128 d]; B tile [n=h_local][k=d]
        const int h = idx >> 7, d = idx & 127;
        g_w1[h >> 7][(h & 127) * ROWE + d] = __float2half_rn(w1[idx]);
    }
    {   // w2: [128 d][512 h]; B tile [n=d][k=h_local]
        const int d = idx >> 9, h = idx & 511;
        g_w2[h >> 7][d * ROWE + (h & 127)] = __float2half_rn(w2[idx]);
    }
}

// ------------- 64x128x128 chunk GEMM, plain fp16, warp tile M32xN64 -------
__device__ __forceinline__ void gemm_chunk(uint32_t aB, uint32_t bB,
                                           float acc[2][8][4]) {
    #pragma unroll
    for (int ks = 0; ks < 8; ++ks) {
        uint32_t a0[4], a1[4];
        ldsm4(a0, aB + ks * 32);
        ldsm4(a1, aB + 16 * ROWB + ks * 32);
        #pragma unroll
        for (int ng = 0; ng < 4; ++ng) {
            uint32_t rb[4];
            ldsm4(rb, bB + ng * (16 * ROWB) + ks * 32);
            mma16816(acc[0][2*ng],   a0, rb[0], rb[1]);
            mma16816(acc[1][2*ng],   a1, rb[0], rb[1]);
            mma16816(acc[0][2*ng+1], a0, rb[2], rb[3]);
            mma16816(acc[1][2*ng+1], a1, rb[2], rb[3]);
        }
    }
}

// ---------------- main fused kernel ----------------
__global__ void __launch_bounds__(THREADS, 2)
fused_ln_mlp_hmma(const float* __restrict__ x,
                  const float* __restrict__ b1,
                  const float* __restrict__ b2,
                  const float* __restrict__ wn,
                  const float* __restrict__ bn,
                  float* __restrict__ out)
{
    extern __shared__ __align__(16) unsigned char smem[];
    const uint32_t sb = smem_u32(smem);

    const int tid  = threadIdx.x;
    const int lane = tid & 31;
    const int warp = tid >> 5;       // 0..3
    const int mw   = warp & 1;       // M block: 32 tokens
    const int nw   = warp >> 1;      // N block: 64 cols
    const long long m0 = (long long)blockIdx.x * TILE_M;

    // prefetch w1(0); LN overlaps the copy
    stage_tile(sb + SM_W, &g_w1[0][0], tid);

    // -------- Stage A: LayerNorm -> xn fp16 padded tile --------
    {
        const float4 wn4 = *(const float4*)(wn + lane * 4);
        const float4 bn4 = *(const float4*)(bn + lane * 4);
        #pragma unroll
        for (int t = 0; t < 16; ++t) {
            const int tok = warp * 16 + t;
            float4 v = *(const float4*)(x + (m0 + tok) * DIMC + lane * 4);
            float s = v.x + v.y + v.z + v.w;
            float q = v.x*v.x + v.y*v.y + v.z*v.z + v.w*v.w;
            #pragma unroll
            for (int o = 16; o > 0; o >>= 1) {
                s += __shfl_xor_sync(0xffffffffu, s, o);
                q += __shfl_xor_sync(0xffffffffu, q, o);
            }
            const float mu  = s * (1.0f / DIMC);
            const float var = q * (1.0f / DIMC) - mu * mu;
            const float r   = rsqrtf(var + EPSV);
            const __half h0 = __float2half_rn((v.x - mu) * r * wn4.x + bn4.x);
            const __half h1 = __float2half_rn((v.y - mu) * r * wn4.y + bn4.y);
            const __half h2 = __float2half_rn((v.z - mu) * r * wn4.z + bn4.z);
            const __half h3 = __float2half_rn((v.w - mu) * r * wn4.w + bn4.w);
            const uint32_t off = (uint32_t)tok * ROWB + lane * 8;
            *(uint2*)(smem + SM_XNH + off) = make_uint2(pack2(h0, h1), pack2(h2, h3));
        }
    }

    CP_WAIT0();
    __syncthreads();   // xn tile + w1(0) visible

    // per-thread ldmatrix base addresses (same scheme as R4, verified)
    const uint32_t a_off = (uint32_t)(mw * 32 + (lane & 15)) * ROWB + ((lane >> 4) << 4);
    const uint32_t b_off = (uint32_t)(nw * 64 + (lane & 7) + ((lane >> 4) << 3)) * ROWB
                         + (((lane >> 3) & 1) << 4);

    float acc2[2][8][4];
    #pragma unroll
    for (int i = 0; i < 2; ++i)
        #pragma unroll
        for (int j = 0; j < 8; ++j)
            #pragma unroll
            for (int k = 0; k < 4; ++k) acc2[i][j][k] = 0.0f;

    for (int c = 0; c < 4; ++c) {
        // ---- G1: acc1 = xn x w1c ----
        float acc1[2][8][4];
        #pragma unroll
        for (int i = 0; i < 2; ++i)
            #pragma unroll
            for (int j = 0; j < 8; ++j)
                #pragma unroll
                for (int k = 0; k < 4; ++k) acc1[i][j][k] = 0.0f;

        gemm_chunk(sb + SM_XNH + a_off, sb + SM_W + b_off, acc1);
        __syncthreads();   // all warps done reading W(w1c)

        // issue w2(c) copy; epilogue math overlaps it
        stage_tile(sb + SM_W, &g_w2[c][0], tid);

        // ---- epilogue G1: +b1, relu -> fp16 Hc tile ----
        {
            const float* b1c = b1 + c * 128;
            #pragma unroll
            for (int mt = 0; mt < 2; ++mt) {
                const int row0 = mw * 32 + mt * 16 + (lane >> 2);
                #pragma unroll
                for (int nt = 0; nt < 8; ++nt) {
                    const int col = nw * 64 + nt * 8 + (lane & 3) * 2;
                    const float bb0 = __ldg(b1c + col), bb1 = __ldg(b1c + col + 1);
                    const __half h0 = __float2half_rn(fmaxf(acc1[mt][nt][0] + bb0, 0.0f));
                    const __half h1 = __float2half_rn(fmaxf(acc1[mt][nt][1] + bb1, 0.0f));
                    const __half h2 = __float2half_rn(fmaxf(acc1[mt][nt][2] + bb0, 0.0f));
                    const __half h3 = __float2half_rn(fmaxf(acc1[mt][nt][3] + bb1, 0.0f));
                    const uint32_t o0 = (uint32_t)row0 * ROWB + col * 2;
                    *(uint32_t*)(smem + SM_HCH + o0)            = pack2(h0, h1);
                    *(uint32_t*)(smem + SM_HCH + o0 + 8 * ROWB) = pack2(h2, h3);
                }
            }
        }

        CP_WAIT0();
        __syncthreads();   // Hc visible + w2(c) staged

        // ---- G2: acc2 += Hc x w2c ----
        gemm_chunk(sb + SM_HCH + a_off, sb + SM_W + b_off, acc2);
        __syncthreads();   // all warps done reading W(w2c) + Hc

        // ---- stage w1(c+1) ----
        if (c < 3) {
            stage_tile(sb + SM_W, &g_w1[c + 1][0], tid);
            CP_WAIT0();
            __syncthreads();
        }
    }

    // -------- final epilogue: acc2 + b2 -> out --------
    #pragma unroll
    for (int mt = 0; mt < 2; ++mt) {
        const long long row0 = m0 + mw * 32 + mt * 16 + (lane >> 2);
        #pragma unroll
        for (int nt = 0; nt < 8; ++nt) {
            const int col = nw * 64 + nt * 8 + (lane & 3) * 2;
            const float bb0 = __ldg(b2 + col), bb1 = __ldg(b2 + col + 1);
            float2 u, w;
            u.x = acc2[mt][nt][0] + bb0;  u.y = acc2[mt][nt][1] + bb1;
            w.x = acc2[mt][nt][2] + bb0;  w.y = acc2[mt][nt][3] + bb1;
            *(float2*)(out + row0 * DIMC + col)       = u;
            *(float2*)(out + (row0 + 8) * DIMC + col) = w;
        }
    }
}

extern "C" void kernel_launch(void* const* d_in, const int* in_sizes, int n_in,
                              void* d_out, int out_size) {
    const float* x  = (const float*)d_in[0];
    const float* w1 = (const float*)d_in[1];
    const float* w2 = (const float*)d_in[2];
    const float* b1 = (const float*)d_in[3];
    const float* b2 = (const float*)d_in[4];
    const float* wn = (const float*)d_in[5];
    const float* bn = (const float*)d_in[6];
    float* out = (float*)d_out;

    prep_weights<<<256, 256>>>(w1, w2);

    const int T = in_sizes[0] / DIMC;        // 262144 tokens
    const int grid = T / TILE_M;             // 4096 CTAs

    cudaFuncSetAttribute(fused_ln_mlp_hmma,
                         cudaFuncAttributeMaxDynamicSharedMemorySize, SM_TOTAL);
    fused_ln_mlp_hmma<<<grid, THREADS, SM_TOTAL>>>(x, b1, b2, wn, bn, out);
}

// round 7
// speedup vs baseline: 8.0865x; 1.0261x over previous
#include <cuda_runtime.h>
#include <cuda_fp16.h>
#include <cstdint>

#define DIMC 128
#define HID  512
#define TILE_M 64
#define THREADS 128
#define EPSV 1e-5f

#define ROWE 136                       // fp16 elems per padded row (272 B)
#define ROWB 272
#define ATILE_BYTES (64 * ROWB)        // 17408
#define WTILE_BYTES (128 * ROWB)       // 34816

// ---- smem layout (bytes): 104448 total -> 2 CTAs/SM
#define SM_XNH 0
#define SM_HCH (SM_XNH + ATILE_BYTES)
#define SM_W0  (SM_HCH + ATILE_BYTES)          // w1 chunks
#define SM_W1  (SM_W0 + WTILE_BYTES)           // w2 chunks
#define SM_TOTAL (SM_W1 + WTILE_BYTES)         // 104448 B

// ---- pre-converted fp16 weight images
__device__ __align__(16) __half g_w1[4][128 * ROWE];
__device__ __align__(16) __half g_w2[4][128 * ROWE];

// ---------------- PTX helpers (baseline ISA only) ----------
__device__ __forceinline__ uint32_t smem_u32(const void* p) {
    uint32_t a;
    asm("{ .reg .u64 t; cvta.to.shared.u64 t, %1; cvt.u32.u64 %0, t; }" : "=r"(a) : "l"(p));
    return a;
}

__device__ __forceinline__ void ldsm4(uint32_t r[4], uint32_t addr) {
    asm volatile("ldmatrix.sync.aligned.m8n8.x4.shared.b16 {%0,%1,%2,%3}, [%4];"
                 : "=r"(r[0]), "=r"(r[1]), "=r"(r[2]), "=r"(r[3]) : "r"(addr));
}

__device__ __forceinline__ void mma16816(float c[4], const uint32_t a[4],
                                         uint32_t b0, uint32_t b1) {
    asm volatile(
        "mma.sync.aligned.m16n8k16.row.col.f32.f16.f16.f32 "
        "{%0,%1,%2,%3}, {%4,%5,%6,%7}, {%8,%9}, {%0,%1,%2,%3};"
        : "+f"(c[0]), "+f"(c[1]), "+f"(c[2]), "+f"(c[3])
        : "r"(a[0]), "r"(a[1]), "r"(a[2]), "r"(a[3]), "r"(b0), "r"(b1));
}

__device__ __forceinline__ void cpasync16(uint32_t dst, const void* src) {
    asm volatile("cp.async.cg.shared.global [%0], [%1], 16;" :: "r"(dst), "l"(src));
}
#define CP_COMMIT() asm volatile("cp.async.commit_group;" ::: "memory")
#define CP_WAIT0()  asm volatile("cp.async.wait_group 0;" ::: "memory")
#define CP_WAIT1()  asm volatile("cp.async.wait_group 1;" ::: "memory")

__device__ __forceinline__ uint32_t pack2(__half a, __half b) {
    __half2 t; t.x = a; t.y = b;
    return *(uint32_t*)&t;
}

// stage one 34816 B weight tile (gmem -> smem): 2176 x 16B, 17 per thread
__device__ __forceinline__ void stage_tile(uint32_t dst, const void* src, int tid) {
    #pragma unroll
    for (int i = 0; i < 17; ++i) {
        const uint32_t off = (uint32_t)(tid + i * THREADS) * 16;
        cpasync16(dst + off, (const char*)src + off);
    }
    CP_COMMIT();
}

// ---------------- prep: weights -> fp16 padded images ----------
__global__ void prep_weights(const float* __restrict__ w1, const float* __restrict__ w2) {
    const int idx = blockIdx.x * blockDim.x + threadIdx.x;   // 0..65535
    {   // w1: [512 h][128 d]; B tile [n=h_local][k=d]
        const int h = idx >> 7, d = idx & 127;
        g_w1[h >> 7][(h & 127) * ROWE + d] = __float2half_rn(w1[idx]);
    }
    {   // w2: [128 d][512 h]; B tile [n=d][k=h_local]
        const int d = idx >> 9, h = idx & 511;
        g_w2[h >> 7][d * ROWE + (h & 127)] = __float2half_rn(w2[idx]);
    }
}

// ------------- 64x128x128 chunk GEMM, plain fp16, warp tile M32xN64 -------
__device__ __forceinline__ void gemm_chunk(uint32_t aB, uint32_t bB,
                                           float acc[2][8][4]) {
    #pragma unroll
    for (int ks = 0; ks < 8; ++ks) {
        uint32_t a0[4], a1[4];
        ldsm4(a0, aB + ks * 32);
        ldsm4(a1, aB + 16 * ROWB + ks * 32);
        #pragma unroll
        for (int ng = 0; ng < 4; ++ng) {
            uint32_t rb[4];
            ldsm4(rb, bB + ng * (16 * ROWB) + ks * 32);
            mma16816(acc[0][2*ng],   a0, rb[0], rb[1]);
            mma16816(acc[1][2*ng],   a1, rb[0], rb[1]);
            mma16816(acc[0][2*ng+1], a0, rb[2], rb[3]);
            mma16816(acc[1][2*ng+1], a1, rb[2], rb[3]);
        }
    }
}

// ---------------- main fused kernel ----------------
__global__ void __launch_bounds__(THREADS, 2)
fused_ln_mlp_hmma(const float* __restrict__ x,
                  const float* __restrict__ b1,
                  const float* __restrict__ b2,
                  const float* __restrict__ wn,
                  const float* __restrict__ bn,
                  float* __restrict__ out)
{
    extern __shared__ __align__(16) unsigned char smem[];
    const uint32_t sb = smem_u32(smem);

    const int tid  = threadIdx.x;
    const int lane = tid & 31;
    const int warp = tid >> 5;       // 0..3
    const int mw   = warp & 1;       // M block: 32 tokens
    const int nw   = warp >> 1;      // N block: 64 cols
    const long long m0 = (long long)blockIdx.x * TILE_M;

    // prefetch w1(0) [group A0] and w2(0) [group B0]; LN overlaps the copies
    stage_tile(sb + SM_W0, &g_w1[0][0], tid);
    stage_tile(sb + SM_W1, &g_w2[0][0], tid);

    // -------- Stage A: LayerNorm -> xn fp16 padded tile --------
    {
        const float4 wn4 = *(const float4*)(wn + lane * 4);
        const float4 bn4 = *(const float4*)(bn + lane * 4);
        #pragma unroll
        for (int t = 0; t < 16; ++t) {
            const int tok = warp * 16 + t;
            float4 v = *(const float4*)(x + (m0 + tok) * DIMC + lane * 4);
            float s = v.x + v.y + v.z + v.w;
            float q = v.x*v.x + v.y*v.y + v.z*v.z + v.w*v.w;
            #pragma unroll
            for (int o = 16; o > 0; o >>= 1) {
                s += __shfl_xor_sync(0xffffffffu, s, o);
                q += __shfl_xor_sync(0xffffffffu, q, o);
            }
            const float mu  = s * (1.0f / DIMC);
            const float var = q * (1.0f / DIMC) - mu * mu;
            const float r   = rsqrtf(var + EPSV);
            const __half h0 = __float2half_rn((v.x - mu) * r * wn4.x + bn4.x);
            const __half h1 = __float2half_rn((v.y - mu) * r * wn4.y + bn4.y);
            const __half h2 = __float2half_rn((v.z - mu) * r * wn4.z + bn4.z);
            const __half h3 = __float2half_rn((v.w - mu) * r * wn4.w + bn4.w);
            const uint32_t off = (uint32_t)tok * ROWB + lane * 8;
            *(uint2*)(smem + SM_XNH + off) = make_uint2(pack2(h0, h1), pack2(h2, h3));
        }
    }

    CP_WAIT1();        // A0 complete (B0 may still be in flight)
    __syncthreads();   // xn tile + w1(0) visible

    // per-thread ldmatrix base addresses
    const uint32_t a_off = (uint32_t)(mw * 32 + (lane & 15)) * ROWB + ((lane >> 4) << 4);
    const uint32_t b_off = (uint32_t)(nw * 64 + (lane & 7) + ((lane >> 4) << 3)) * ROWB
                         + (((lane >> 3) & 1) << 4);

    float acc2[2][8][4];
    #pragma unroll
    for (int i = 0; i < 2; ++i)
        #pragma unroll
        for (int j = 0; j < 8; ++j)
            #pragma unroll
            for (int k = 0; k < 4; ++k) acc2[i][j][k] = 0.0f;

    // pending-group invariant at loop top of chunk c: {B(c), [A(c) done]}
    for (int c = 0; c < 4; ++c) {
        // ---- G1: acc1 = xn x w1(c)  [reads W0] ----
        float acc1[2][8][4];
        #pragma unroll
        for (int i = 0; i < 2; ++i)
            #pragma unroll
            for (int j = 0; j < 8; ++j)
                #pragma unroll
                for (int k = 0; k < 4; ++k) acc1[i][j][k] = 0.0f;

        gemm_chunk(sb + SM_XNH + a_off, sb + SM_W0 + b_off, acc1);
        __syncthreads();                       // all warps done reading W0

        // prefetch w1(c+1) into W0 [group A(c+1)]; hidden under epi + G2
        if (c < 3) stage_tile(sb + SM_W0, &g_w1[c + 1][0], tid);

        // ---- epilogue G1: +b1, relu -> fp16 Hc tile ----
        {
            const float* b1c = b1 + c * 128;
            #pragma unroll
            for (int mt = 0; mt < 2; ++mt) {
                const int row0 = mw * 32 + mt * 16 + (lane >> 2);
                #pragma unroll
                for (int nt = 0; nt < 8; ++nt) {
                    const int col = nw * 64 + nt * 8 + (lane & 3) * 2;
                    const float bb0 = __ldg(b1c + col), bb1 = __ldg(b1c + col + 1);
                    const __half h0 = __float2half_rn(fmaxf(acc1[mt][nt][0] + bb0, 0.0f));
                    const __half h1 = __float2half_rn(fmaxf(acc1[mt][nt][1] + bb1, 0.0f));
                    const __half h2 = __float2half_rn(fmaxf(acc1[mt][nt][2] + bb0, 0.0f));
                    const __half h3 = __float2half_rn(fmaxf(acc1[mt][nt][3] + bb1, 0.0f));
                    const uint32_t o0 = (uint32_t)row0 * ROWB + col * 2;
                    *(uint32_t*)(smem + SM_HCH + o0)            = pack2(h0, h1);
                    *(uint32_t*)(smem + SM_HCH + o0 + 8 * ROWB) = pack2(h2, h3);
                }
            }
        }

        // wait B(c): pending = {B(c) older, A(c+1) newer} -> wait_group 1
        if (c < 3) CP_WAIT1(); else CP_WAIT0();
        __syncthreads();   // Hc visible + w2(c) visible to all

        // ---- G2: acc2 += Hc x w2(c)  [reads W1] ----
        gemm_chunk(sb + SM_HCH + a_off, sb + SM_W1 + b_off, acc2);
        __syncthreads();   // all warps done reading W1 + Hc

        // prefetch w2(c+1) into W1 [group B(c+1)]; hidden under G1(c+1) + epi
        if (c < 3) {
            stage_tile(sb + SM_W1, &g_w2[c + 1][0], tid);
            // wait A(c+1): pending = {A(c+1) older, B(c+1) newer} -> wait_group 1
            CP_WAIT1();
            __syncthreads();   // w1(c+1) visible to all
        }
    }

    // -------- final epilogue: acc2 + b2 -> out --------
    #pragma unroll
    for (int mt = 0; mt < 2; ++mt) {
        const long long row0 = m0 + mw * 32 + mt * 16 + (lane >> 2);
        #pragma unroll
        for (int nt = 0; nt < 8; ++nt) {
            const int col = nw * 64 + nt * 8 + (lane & 3) * 2;
            const float bb0 = __ldg(b2 + col), bb1 = __ldg(b2 + col + 1);
            float2 u, w;
            u.x = acc2[mt][nt][0] + bb0;  u.y = acc2[mt][nt][1] + bb1;
            w.x = acc2[mt][nt][2] + bb0;  w.y = acc2[mt][nt][3] + bb1;
            *(float2*)(out + row0 * DIMC + col)       = u;
            *(float2*)(out + (row0 + 8) * DIMC + col) = w;
        }
    }
}

extern "C" void kernel_launch(void* const* d_in, const int* in_sizes, int n_in,
                              void* d_out, int out_size) {
    const float* x  = (const float*)d_in[0];
    const float* w1 = (const float*)d_in[1];
    const float* w2 = (const float*)d_in[2];
    const float* b1 = (const float*)d_in[3];
    const float* b2 = (const float*)d_in[4];
    const float* wn = (const float*)d_in[5];
    const float* bn = (const float*)d_in[6];
    float* out = (float*)d_out;

    prep_weights<<<256, 256>>>(w1, w2);

    const int T = in_sizes[0] / DIMC;        // 262144 tokens
    const int grid = T / TILE_M;             // 4096 CTAs

    cudaFuncSetAttribute(fused_ln_mlp_hmma,
                         cudaFuncAttributeMaxDynamicSharedMemorySize, SM_TOTAL);
    fused_ln_mlp_hmma<<<grid, THREADS, SM_TOTAL>>>(x, b1, b2, wn, bn, out);
}

// round 8
// speedup vs baseline: 8.3307x; 1.0302x over previous
#include <cuda_runtime.h>
#include <cuda_fp16.h>
#include <cstdint>

#define DIMC 128
#define HID  512
#define TILE_M 64
#define THREADS 128
#define EPSV 1e-5f

#define ROWE 136                       // fp16 elems per padded row (272 B)
#define ROWB 272
#define ATILE_BYTES (64 * ROWB)        // 17408

// ---- smem layout (bytes): xn + 4 H chunk buffers = 87040 -> 2 CTAs/SM
#define SM_XN 0
#define SM_H  (SM_XN + ATILE_BYTES)
#define SM_TOTAL (SM_H + 4 * ATILE_BYTES)   // 87040

// ---- fragment-ordered fp16 weight images: [chunk][nw][iter=ks*4+ng][lane]
// each uint4 = the 4 B-fragment regs (rb0..rb3) for one (ks,ng) MMA pair.
__device__ __align__(16) uint4 g_w1f[4][2][32][32];
__device__ __align__(16) uint4 g_w2f[4][2][32][32];

// ---------------- PTX helpers (baseline ISA only) ----------
__device__ __forceinline__ uint32_t smem_u32(const void* p) {
    uint32_t a;
    asm("{ .reg .u64 t; cvta.to.shared.u64 t, %1; cvt.u32.u64 %0, t; }" : "=r"(a) : "l"(p));
    return a;
}

__device__ __forceinline__ void ldsm4(uint32_t r[4], uint32_t addr) {
    asm volatile("ldmatrix.sync.aligned.m8n8.x4.shared.b16 {%0,%1,%2,%3}, [%4];"
                 : "=r"(r[0]), "=r"(r[1]), "=r"(r[2]), "=r"(r[3]) : "r"(addr));
}

__device__ __forceinline__ void mma16816(float c[4], const uint32_t a[4],
                                         uint32_t b0, uint32_t b1) {
    asm volatile(
        "mma.sync.aligned.m16n8k16.row.col.f32.f16.f16.f32 "
        "{%0,%1,%2,%3}, {%4,%5,%6,%7}, {%8,%9}, {%0,%1,%2,%3};"
        : "+f"(c[0]), "+f"(c[1]), "+f"(c[2]), "+f"(c[3])
        : "r"(a[0]), "r"(a[1]), "r"(a[2]), "r"(a[3]), "r"(b0), "r"(b1));
}

__device__ __forceinline__ uint32_t pack2(__half a, __half b) {
    __half2 t; t.x = a; t.y = b;
    return *(uint32_t*)&t;
}

// ---------------- prep: weights -> fragment-ordered fp16 images ----------
// idx decodes (mat, c, nw, iter, lane); each thread emits one uint4 fragment.
__global__ void prep_weights(const float* __restrict__ w1, const float* __restrict__ w2) {
    const int idx  = blockIdx.x * blockDim.x + threadIdx.x;   // 0..16383
    const int lane = idx & 31;
    const int iter = (idx >> 5) & 31;
    const int nw   = (idx >> 10) & 1;
    const int c    = (idx >> 11) & 3;
    const int mat  = idx >> 13;

    const int ks = iter >> 2, ng = iter & 3;
    const int n0 = nw * 64 + ng * 16 + (lane >> 2);
    const int k0 = ks * 16 + (lane & 3) * 2;

    uint4 v;
    if (mat == 0) {
        // w1: [512 h][128 d]; B element (n,k) = w1[c*128+n][k]
        #define E1(n, k) __float2half_rn(w1[(size_t)(c * 128 + (n)) * DIMC + (k)])
        v.x = pack2(E1(n0,     k0),     E1(n0,     k0 + 1));
        v.y = pack2(E1(n0,     k0 + 8), E1(n0,     k0 + 9));
        v.z = pack2(E1(n0 + 8, k0),     E1(n0 + 8, k0 + 1));
        v.w = pack2(E1(n0 + 8, k0 + 8), E1(n0 + 8, k0 + 9));
        #undef E1
        g_w1f[c][nw][iter][lane] = v;
    } else {
        // w2: [128 d][512 h]; B element (n,k) = w2[n][c*128+k]
        #define E2(n, k) __float2half_rn(w2[(size_t)(n) * HID + c * 128 + (k)])
        v.x = pack2(E2(n0,     k0),     E2(n0,     k0 + 1));
        v.y = pack2(E2(n0,     k0 + 8), E2(n0,     k0 + 9));
        v.z = pack2(E2(n0 + 8, k0),     E2(n0 + 8, k0 + 1));
        v.w = pack2(E2(n0 + 8, k0 + 8), E2(n0 + 8, k0 + 9));
        #undef E2
        g_w2f[c][nw][iter][lane] = v;
    }
}

// ---------------- main fused kernel ----------------
__global__ void __launch_bounds__(THREADS, 2)
fused_ln_mlp_hmma(const float* __restrict__ x,
                  const float* __restrict__ b1,
                  const float* __restrict__ b2,
                  const float* __restrict__ wn,
                  const float* __restrict__ bn,
                  float* __restrict__ out)
{
    extern __shared__ __align__(16) unsigned char smem[];
    const uint32_t sb = smem_u32(smem);

    const int tid  = threadIdx.x;
    const int lane = tid & 31;
    const int warp = tid >> 5;       // 0..3
    const int mw   = warp & 1;       // M block: 32 tokens
    const int nw   = warp >> 1;      // N block: 64 cols
    const long long m0 = (long long)blockIdx.x * TILE_M;

    // -------- Stage A: LayerNorm -> xn fp16 padded tile --------
    {
        const float4 wn4 = *(const float4*)(wn + lane * 4);
        const float4 bn4 = *(const float4*)(bn + lane * 4);
        #pragma unroll
        for (int t = 0; t < 16; ++t) {
            const int tok = warp * 16 + t;
            float4 v = *(const float4*)(x + (m0 + tok) * DIMC + lane * 4);
            float s = v.x + v.y + v.z + v.w;
            float q = v.x*v.x + v.y*v.y + v.z*v.z + v.w*v.w;
            #pragma unroll
            for (int o = 16; o > 0; o >>= 1) {
                s += __shfl_xor_sync(0xffffffffu, s, o);
                q += __shfl_xor_sync(0xffffffffu, q, o);
            }
            const float mu  = s * (1.0f / DIMC);
            const float var = q * (1.0f / DIMC) - mu * mu;
            const float r   = rsqrtf(var + EPSV);
            const __half h0 = __float2half_rn((v.x - mu) * r * wn4.x + bn4.x);
            const __half h1 = __float2half_rn((v.y - mu) * r * wn4.y + bn4.y);
            const __half h2 = __float2half_rn((v.z - mu) * r * wn4.z + bn4.z);
            const __half h3 = __float2half_rn((v.w - mu) * r * wn4.w + bn4.w);
            const uint32_t off = (uint32_t)tok * ROWB + lane * 8;
            *(uint2*)(smem + SM_XN + off) = make_uint2(pack2(h0, h1), pack2(h2, h3));
        }
    }
    __syncthreads();   // xn visible

    // per-thread A ldmatrix addressing: mt block at +16 rows
    const uint32_t a_row = (uint32_t)(mw * 32 + (lane & 15)) * ROWB + ((lane >> 4) << 4);

    // -------- preload xn A-fragments for ALL G1 chunks (reused 4x) --------
    uint32_t ax[2][8][4];
    #pragma unroll
    for (int mt = 0; mt < 2; ++mt)
        #pragma unroll
        for (int kf = 0; kf < 8; ++kf)
            ldsm4(ax[mt][kf], sb + SM_XN + a_row + (uint32_t)mt * (16 * ROWB) + kf * 32);

    // -------- Phase 1: G1(c) + epilogue -> H(c), c = 0..3, no barriers ----
    for (int c = 0; c < 4; ++c) {
        float acc1[2][8][4];
        #pragma unroll
        for (int i = 0; i < 2; ++i)
            #pragma unroll
            for (int j = 0; j < 8; ++j)
                #pragma unroll
                for (int k = 0; k < 4; ++k) acc1[i][j][k] = 0.0f;

        const uint4* __restrict__ bp = &g_w1f[c][nw][0][lane];
        #pragma unroll
        for (int ks = 0; ks < 8; ++ks) {
            #pragma unroll
            for (int ng = 0; ng < 4; ++ng) {
                const uint4 rb = __ldg(bp + (ks * 4 + ng) * 32);
                mma16816(acc1[0][2*ng],   ax[0][ks], rb.x, rb.y);
                mma16816(acc1[1][2*ng],   ax[1][ks], rb.x, rb.y);
                mma16816(acc1[0][2*ng+1], ax[0][ks], rb.z, rb.w);
                mma16816(acc1[1][2*ng+1], ax[1][ks], rb.z, rb.w);
            }
        }

        // epilogue: +b1, relu -> fp16 H(c) tile
        const float* b1c = b1 + c * 128;
        const uint32_t hbase = SM_H + (uint32_t)c * ATILE_BYTES;
        #pragma unroll
        for (int mt = 0; mt < 2; ++mt) {
            const int row0 = mw * 32 + mt * 16 + (lane >> 2);
            #pragma unroll
            for (int nt = 0; nt < 8; ++nt) {
                const int col = nw * 64 + nt * 8 + (lane & 3) * 2;
                const float bb0 = __ldg(b1c + col), bb1 = __ldg(b1c + col + 1);
                const __half h0 = __float2half_rn(fmaxf(acc1[mt][nt][0] + bb0, 0.0f));
                const __half h1 = __float2half_rn(fmaxf(acc1[mt][nt][1] + bb1, 0.0f));
                const __half h2 = __float2half_rn(fmaxf(acc1[mt][nt][2] + bb0, 0.0f));
                const __half h3 = __float2half_rn(fmaxf(acc1[mt][nt][3] + bb1, 0.0f));
                const uint32_t o0 = hbase + (uint32_t)row0 * ROWB + col * 2;
                *(uint32_t*)(smem + o0)            = pack2(h0, h1);
                *(uint32_t*)(smem + o0 + 8 * ROWB) = pack2(h2, h3);
            }
        }
    }

    __syncthreads();   // ALL H chunks visible to all warps

    // -------- Phase 2: G2(c), c = 0..3, acc2 accumulates, no barriers -----
    float acc2[2][8][4];
    #pragma unroll
    for (int i = 0; i < 2; ++i)
        #pragma unroll
        for (int j = 0; j < 8; ++j)
            #pragma unroll
            for (int k = 0; k < 4; ++k) acc2[i][j][k] = 0.0f;

    for (int c = 0; c < 4; ++c) {
        const uint32_t hA = sb + SM_H + (uint32_t)c * ATILE_BYTES + a_row;
        const uint4* __restrict__ bp = &g_w2f[c][nw][0][lane];
        #pragma unroll
        for (int ks = 0; ks < 8; ++ks) {
            uint32_t a0[4], a1[4];
            ldsm4(a0, hA + ks * 32);
            ldsm4(a1, hA + 16 * ROWB + ks * 32);
            #pragma unroll
            for (int ng = 0; ng < 4; ++ng) {
                const uint4 rb = __ldg(bp + (ks * 4 + ng) * 32);
                mma16816(acc2[0][2*ng],   a0, rb.x, rb.y);
                mma16816(acc2[1][2*ng],   a1, rb.x, rb.y);
                mma16816(acc2[0][2*ng+1], a0, rb.z, rb.w);
                mma16816(acc2[1][2*ng+1], a1, rb.z, rb.w);
            }
        }
    }

    // -------- final epilogue: acc2 + b2 -> out --------
    #pragma unroll
    for (int mt = 0; mt < 2; ++mt) {
        const long long row0 = m0 + mw * 32 + mt * 16 + (lane >> 2);
        #pragma unroll
        for (int nt = 0; nt < 8; ++nt) {
            const int col = nw * 64 + nt * 8 + (lane & 3) * 2;
            const float bb0 = __ldg(b2 + col), bb1 = __ldg(b2 + col + 1);
            float2 u, w;
            u.x = acc2[mt][nt][0] + bb0;  u.y = acc2[mt][nt][1] + bb1;
            w.x = acc2[mt][nt][2] + bb0;  w.y = acc2[mt][nt][3] + bb1;
            *(float2*)(out + row0 * DIMC + col)       = u;
            *(float2*)(out + (row0 + 8) * DIMC + col) = w;
        }
    }
}

extern "C" void kernel_launch(void* const* d_in, const int* in_sizes, int n_in,
                              void* d_out, int out_size) {
    const float* x  = (const float*)d_in[0];
    const float* w1 = (const float*)d_in[1];
    const float* w2 = (const float*)d_in[2];
    const float* b1 = (const float*)d_in[3];
    const float* b2 = (const float*)d_in[4];
    const float* wn = (const float*)d_in[5];
    const float* bn = (const float*)d_in[6];
    float* out = (float*)d_out;

    prep_weights<<<64, 256>>>(w1, w2);

    const int T = in_sizes[0] / DIMC;        // 262144 tokens
    const int grid = T / TILE_M;             // 4096 CTAs

    cudaFuncSetAttribute(fused_ln_mlp_hmma,
                         cudaFuncAttributeMaxDynamicSharedMemorySize, SM_TOTAL);
    fused_ln_mlp_hmma<<<grid, THREADS, SM_TOTAL>>>(x, b1, b2, wn, bn, out);
}

// round 9
// speedup vs baseline: 9.6175x; 1.1545x over previous
#include <cuda_runtime.h>
#include <cuda_fp16.h>
#include <cstdint>

#define DIMC 128
#define HID  512
#define TILE_M 64
#define THREADS 128
#define EPSV 1e-5f

#define ROWE 136
#define ROWB 272
#define ATILE_BYTES (64 * ROWB)        // 17408

// ---- smem: xn + 4 H chunk buffers = 87040 -> 2 CTAs/SM
#define SM_XN 0
#define SM_H  (SM_XN + ATILE_BYTES)
#define SM_TOTAL (SM_H + 4 * ATILE_BYTES)

// ---- fragment-ordered fp16 weight images: [chunk][nw][iter=ks*4+ng][lane]
__device__ __align__(16) uint4 g_w1f[4][2][32][32];
__device__ __align__(16) uint4 g_w2f[4][2][32][32];

// ---------------- PTX helpers ----------------
__device__ __forceinline__ uint32_t smem_u32(const void* p) {
    uint32_t a;
    asm("{ .reg .u64 t; cvta.to.shared.u64 t, %1; cvt.u32.u64 %0, t; }" : "=r"(a) : "l"(p));
    return a;
}

__device__ __forceinline__ void ldsm4(uint32_t r[4], uint32_t addr) {
    asm volatile("ldmatrix.sync.aligned.m8n8.x4.shared.b16 {%0,%1,%2,%3}, [%4];"
                 : "=r"(r[0]), "=r"(r[1]), "=r"(r[2]), "=r"(r[3]) : "r"(addr));
}

__device__ __forceinline__ void mma16816(float c[4], const uint32_t a[4],
                                         uint32_t b0, uint32_t b1) {
    asm volatile(
        "mma.sync.aligned.m16n8k16.row.col.f32.f16.f16.f32 "
        "{%0,%1,%2,%3}, {%4,%5,%6,%7}, {%8,%9}, {%0,%1,%2,%3};"
        : "+f"(c[0]), "+f"(c[1]), "+f"(c[2]), "+f"(c[3])
        : "r"(a[0]), "r"(a[1]), "r"(a[2]), "r"(a[3]), "r"(b0), "r"(b1));
}

// pack two f32 -> f16x2 (lo in low half, hi in high half)
__device__ __forceinline__ uint32_t pack_f16x2(float lo, float hi) {
    uint32_t r;
    asm("cvt.rn.f16x2.f32 %0, %1, %2;" : "=r"(r) : "f"(hi), "f"(lo));
    return r;
}

__device__ __forceinline__ uint32_t relu_bias_h2(uint32_t v, uint32_t bias) {
    const __half2 z = __float2half2_rn(0.0f);
    __half2 h = __hadd2(*(__half2*)&v, *(__half2*)&bias);
    h = __hmax2(h, z);
    return *(uint32_t*)&h;
}

__device__ __forceinline__ uint32_t pack2h(__half a, __half b) {
    __half2 t; t.x = a; t.y = b;
    return *(uint32_t*)&t;
}

// ---------------- prep: weights -> fragment-ordered fp16 images ----------
__global__ void prep_weights(const float* __restrict__ w1, const float* __restrict__ w2) {
    const int idx  = blockIdx.x * blockDim.x + threadIdx.x;   // 0..16383
    const int lane = idx & 31;
    const int iter = (idx >> 5) & 31;
    const int nw   = (idx >> 10) & 1;
    const int c    = (idx >> 11) & 3;
    const int mat  = idx >> 13;

    const int ks = iter >> 2, ng = iter & 3;
    const int n0 = nw * 64 + ng * 16 + (lane >> 2);
    const int k0 = ks * 16 + (lane & 3) * 2;

    uint4 v;
    if (mat == 0) {
        #define E1(n, k) __float2half_rn(w1[(size_t)(c * 128 + (n)) * DIMC + (k)])
        v.x = pack2h(E1(n0,     k0),     E1(n0,     k0 + 1));
        v.y = pack2h(E1(n0,     k0 + 8), E1(n0,     k0 + 9));
        v.z = pack2h(E1(n0 + 8, k0),     E1(n0 + 8, k0 + 1));
        v.w = pack2h(E1(n0 + 8, k0 + 8), E1(n0 + 8, k0 + 9));
        #undef E1
        g_w1f[c][nw][iter][lane] = v;
    } else {
        #define E2(n, k) __float2half_rn(w2[(size_t)(n) * HID + c * 128 + (k)])
        v.x = pack2h(E2(n0,     k0),     E2(n0,     k0 + 1));
        v.y = pack2h(E2(n0,     k0 + 8), E2(n0,     k0 + 9));
        v.z = pack2h(E2(n0 + 8, k0),     E2(n0 + 8, k0 + 1));
        v.w = pack2h(E2(n0 + 8, k0 + 8), E2(n0 + 8, k0 + 9));
        #undef E2
        g_w2f[c][nw][iter][lane] = v;
    }
}

// one ks step of a chunk GEMM: 2 A-LDSM + 4 B-LDG + 16 MMA
__device__ __forceinline__ void gemm_ks(uint32_t aAddr, const uint4* __restrict__ bp,
                                        int ks, float acc[2][8][4]) {
    uint32_t a0[4], a1[4];
    ldsm4(a0, aAddr + ks * 32);
    ldsm4(a1, aAddr + 16 * ROWB + ks * 32);
    #pragma unroll
    for (int ng = 0; ng < 4; ++ng) {
        const uint4 rb = __ldg(bp + (ks * 4 + ng) * 32);
        mma16816(acc[0][2*ng],   a0, rb.x, rb.y);
        mma16816(acc[1][2*ng],   a1, rb.x, rb.y);
        mma16816(acc[0][2*ng+1], a0, rb.z, rb.w);
        mma16816(acc[1][2*ng+1], a1, rb.z, rb.w);
    }
}

// ---------------- main fused kernel ----------------
__global__ void __launch_bounds__(THREADS, 2)
fused_ln_mlp_hmma(const float* __restrict__ x,
                  const float* __restrict__ b1,
                  const float* __restrict__ b2,
                  const float* __restrict__ wn,
                  const float* __restrict__ bn,
                  float* __restrict__ out)
{
    extern __shared__ __align__(16) unsigned char smem[];
    const uint32_t sb = smem_u32(smem);

    const int tid  = threadIdx.x;
    const int lane = tid & 31;
    const int warp = tid >> 5;
    const int mw   = warp & 1;
    const int nw   = warp >> 1;
    const long long m0 = (long long)blockIdx.x * TILE_M;

    // -------- Stage A: LayerNorm -> xn fp16 tile --------
    {
        const float4 wn4 = *(const float4*)(wn + lane * 4);
        const float4 bn4 = *(const float4*)(bn + lane * 4);
        #pragma unroll
        for (int t = 0; t < 16; ++t) {
            const int tok = warp * 16 + t;
            float4 v = *(const float4*)(x + (m0 + tok) * DIMC + lane * 4);
            float s = v.x + v.y + v.z + v.w;
            float q = v.x*v.x + v.y*v.y + v.z*v.z + v.w*v.w;
            #pragma unroll
            for (int o = 16; o > 0; o >>= 1) {
                s += __shfl_xor_sync(0xffffffffu, s, o);
                q += __shfl_xor_sync(0xffffffffu, q, o);
            }
            const float mu  = s * (1.0f / DIMC);
            const float var = q * (1.0f / DIMC) - mu * mu;
            const float r   = rsqrtf(var + EPSV);
            const uint32_t p0 = pack_f16x2((v.x - mu) * r * wn4.x + bn4.x,
                                           (v.y - mu) * r * wn4.y + bn4.y);
            const uint32_t p1 = pack_f16x2((v.z - mu) * r * wn4.z + bn4.z,
                                           (v.w - mu) * r * wn4.w + bn4.w);
            const uint32_t off = (uint32_t)tok * ROWB + lane * 8;
            *(uint2*)(smem + SM_XN + off) = make_uint2(p0, p1);
        }
    }
    __syncthreads();

    // per-thread addressing
    const uint32_t a_row = (uint32_t)(mw * 32 + (lane & 15)) * ROWB + ((lane >> 4) << 4);
    const uint32_t aXn   = sb + SM_XN + a_row;
    // H epilogue store base: row = mw*32 + (lane>>2), col = nw*64 + (lane&3)*2
    const uint32_t h_sts0 = (uint32_t)(mw * 32 + (lane >> 2)) * ROWB
                          + (uint32_t)(nw * 64 + (lane & 3) * 2) * 2;
    const int colb = nw * 64 + (lane & 3) * 2;   // bias column base (nt adds 8*nt)

    // -------- Phase 1: pipelined G1 chunks --------
    float accP[2][8][4], accQ[2][8][4];
    uint32_t hp[16][2];

    // chunk 0
    #pragma unroll
    for (int i = 0; i < 2; ++i)
        #pragma unroll
        for (int j = 0; j < 8; ++j)
            #pragma unroll
            for (int k = 0; k < 4; ++k) accP[i][j][k] = 0.0f;
    {
        const uint4* __restrict__ bp = &g_w1f[0][nw][0][lane];
        #pragma unroll
        for (int ks = 0; ks < 8; ++ks) gemm_ks(aXn, bp, ks, accP);
    }

    #pragma unroll
    for (int c = 0; c < 4; ++c) {
        float (*cur)[8][4] = (c & 1) ? accQ : accP;
        float (*nxt)[8][4] = (c & 1) ? accP : accQ;

        // pack epilogue for chunk c: +b1 (half2), relu, -> hp[16][2]
        {
            const float* b1c = b1 + c * 128;
            uint32_t hb[8];
            #pragma unroll
            for (int nt = 0; nt < 8; ++nt)
                hb[nt] = pack_f16x2(__ldg(b1c + colb + nt * 8),
                                    __ldg(b1c + colb + nt * 8 + 1));
            #pragma unroll
            for (int mt = 0; mt < 2; ++mt)
                #pragma unroll
                for (int nt = 0; nt < 8; ++nt) {
                    hp[mt * 8 + nt][0] =
                        relu_bias_h2(pack_f16x2(cur[mt][nt][0], cur[mt][nt][1]), hb[nt]);
                    hp[mt * 8 + nt][1] =
                        relu_bias_h2(pack_f16x2(cur[mt][nt][2], cur[mt][nt][3]), hb[nt]);
                }
        }

        const uint32_t hbase = SM_H + (uint32_t)c * ATILE_BYTES + h_sts0;

        if (c < 3) {
            // next chunk MMA loop with interleaved epilogue stores of chunk c
            #pragma unroll
            for (int i = 0; i < 2; ++i)
                #pragma unroll
                for (int j = 0; j < 8; ++j)
                    #pragma unroll
                    for (int k = 0; k < 4; ++k) nxt[i][j][k] = 0.0f;
            const uint4* __restrict__ bp = &g_w1f[c + 1][nw][0][lane];
            #pragma unroll
            for (int ks = 0; ks < 8; ++ks) {
                gemm_ks(aXn, bp, ks, nxt);
                // store 2 flat groups of chunk c's H
                #pragma unroll
                for (int f = 2 * ks; f < 2 * ks + 2; ++f) {
                    const int mt = f >> 3, nt = f & 7;
                    const uint32_t o0 = hbase + (uint32_t)mt * (16 * ROWB) + nt * 16;
                    *(uint32_t*)(smem + o0)            = hp[f][0];
                    *(uint32_t*)(smem + o0 + 8 * ROWB) = hp[f][1];
                }
            }
        } else {
            #pragma unroll
            for (int f = 0; f < 16; ++f) {
                const int mt = f >> 3, nt = f & 7;
                const uint32_t o0 = hbase + (uint32_t)mt * (16 * ROWB) + nt * 16;
                *(uint32_t*)(smem + o0)            = hp[f][0];
                *(uint32_t*)(smem + o0 + 8 * ROWB) = hp[f][1];
            }
        }
    }

    __syncthreads();   // all H chunks visible

    // -------- Phase 2: G2 chunks, acc2 accumulates --------
    float acc2[2][8][4];
    #pragma unroll
    for (int i = 0; i < 2; ++i)
        #pragma unroll
        for (int j = 0; j < 8; ++j)
            #pragma unroll
            for (int k = 0; k < 4; ++k) acc2[i][j][k] = 0.0f;

    #pragma unroll
    for (int c = 0; c < 4; ++c) {
        const uint32_t hA = sb + SM_H + (uint32_t)c * ATILE_BYTES + a_row;
        const uint4* __restrict__ bp = &g_w2f[c][nw][0][lane];
        #pragma unroll
        for (int ks = 0; ks < 8; ++ks) gemm_ks(hA, bp, ks, acc2);
    }

    // -------- final epilogue: acc2 + b2 -> out --------
    #pragma unroll
    for (int mt = 0; mt < 2; ++mt) {
        const long long row0 = m0 + mw * 32 + mt * 16 + (lane >> 2);
        #pragma unroll
        for (int nt = 0; nt < 8; ++nt) {
            const int col = nw * 64 + nt * 8 + (lane & 3) * 2;
            const float bb0 = __ldg(b2 + col), bb1 = __ldg(b2 + col + 1);
            float2 u, w;
            u.x = acc2[mt][nt][0] + bb0;  u.y = acc2[mt][nt][1] + bb1;
            w.x = acc2[mt][nt][2] + bb0;  w.y = acc2[mt][nt][3] + bb1;
            *(float2*)(out + row0 * DIMC + col)       = u;
            *(float2*)(out + (row0 + 8) * DIMC + col) = w;
        }
    }
}

extern "C" void kernel_launch(void* const* d_in, const int* in_sizes, int n_in,
                              void* d_out, int out_size) {
    const float* x  = (const float*)d_in[0];
    const float* w1 = (const float*)d_in[1];
    const float* w2 = (const float*)d_in[2];
    const float* b1 = (const float*)d_in[3];
    const float* b2 = (const float*)d_in[4];
    const float* wn = (const float*)d_in[5];
    const float* bn = (const float*)d_in[6];
    float* out = (float*)d_out;

    prep_weights<<<64, 256>>>(w1, w2);

    const int T = in_sizes[0] / DIMC;        // 262144 tokens
    const int grid = T / TILE_M;             // 4096 CTAs

    cudaFuncSetAttribute(fused_ln_mlp_hmma,
                         cudaFuncAttributeMaxDynamicSharedMemorySize, SM_TOTAL);
    fused_ln_mlp_hmma<<<grid, THREADS, SM_TOTAL>>>(x, b1, b2, wn, bn, out);
}